// round 4
// baseline (speedup 1.0000x reference)
#include <cuda_runtime.h>
#include <cuda_bf16.h>
#include <mma.h>
#include <math.h>
#include <cstdint>

using namespace nvcuda;

#define NHI 4096
#define NLO 262144
#define NT  (NHI + NLO)      /* 266240 = 1024 * 260 */
#define EHI 65536
#define ELO 524288
#define ET  (EHI + ELO)
#define DIM 128
#define NHEAD 4
#define HDIM 32
#define SCALE 0.17677669529663687f   /* 1/sqrt(32) */

// ---------------- scratch (device globals; no allocation allowed) ----------------
__device__ float g_q[(size_t)NT * DIM];
__device__ float g_k[(size_t)NT * DIM];
__device__ float g_v[(size_t)NT * DIM];
__device__ float g_h[(size_t)NT * DIM];      // skip -> += agg -> LN+relu in place
__device__ int g_dcnt[NT];
__device__ int g_rowptr[NT + 1];
__device__ int g_cursor[NT];
__device__ int g_col[ET];
// W^T bf16 hi/lo images: [matrix 0..3][n 0..127][k 0..127]
__device__ __align__(16) __nv_bfloat16 g_wt_hi[4 * 128 * 128];
__device__ __align__(16) __nv_bfloat16 g_wt_lo[4 * 128 * 128];
// bias broadcast tiles: [matrix][16 rows][128 cols] (all rows identical)
__device__ __align__(16) float g_btile[4 * 16 * 128];

// ---------------- helpers ----------------
__device__ __forceinline__ float warp_sum(float v) {
    #pragma unroll
    for (int o = 16; o; o >>= 1) v += __shfl_xor_sync(0xffffffffu, v, o);
    return v;
}

// ---------------- K0a: prep weights -> W^T bf16 hi/lo ----------------
__global__ void prep_w(const float* __restrict__ Wq, const float* __restrict__ Wk,
                       const float* __restrict__ Wv, const float* __restrict__ Ws)
{
    int idx = blockIdx.x * 256 + threadIdx.x;  // 0..65535
    int m = idx >> 14;       // matrix 0..3
    int n = (idx >> 7) & 127;
    int k = idx & 127;
    const float* W = (m == 0) ? Wq : (m == 1) ? Wk : (m == 2) ? Wv : Ws;
    float w = W[k * 128 + n];
    __nv_bfloat16 hi = __float2bfloat16(w);
    __nv_bfloat16 lo = __float2bfloat16(w - __bfloat162float(hi));
    g_wt_hi[idx] = hi;
    g_wt_lo[idx] = lo;
}

// ---------------- K0b: prep bias tiles ----------------
__global__ void prep_b(const float* __restrict__ bq, const float* __restrict__ bk,
                       const float* __restrict__ bv, const float* __restrict__ bs)
{
    int idx = blockIdx.x * 256 + threadIdx.x;  // 0..8191
    int m = idx >> 11;
    int n = idx & 127;
    const float* B = (m == 0) ? bq : (m == 1) ? bk : (m == 2) ? bv : bs;
    g_btile[idx] = B[n];
}

// ---------------- K1: fused QKV+skip GEMM via HMMA (bf16x3 split) ----------------
#define LDA 136
#define SM_ALO (128 * LDA)
#define SM_BHI (2 * 128 * LDA)
#define SM_BLO (3 * 128 * LDA)
#define SM_BYTES (4 * 128 * LDA * 2)

__global__ void __launch_bounds__(256, 1)
gemm_hmma(const float* __restrict__ xh, const float* __restrict__ xl)
{
    extern __shared__ __nv_bfloat16 sm[];
    const int t = threadIdx.x;
    const int wid = t >> 5;
    const int wm = wid & 3;        // warp row group: 32 rows each
    const int wn = wid >> 2;       // warp col group: 64 cols each

    const int row0 = blockIdx.x * 128;
    const float* X = (row0 < NHI) ? (xh + (size_t)row0 * DIM)
                                  : (xl + (size_t)(row0 - NHI) * DIM);
    #pragma unroll
    for (int j = 0; j < 16; j++) {
        int v = t + 256 * j;            // float4 index 0..4095
        int r = v >> 5;                 // row 0..127
        int k0 = (v & 31) * 4;          // k 0..124
        float4 x = ((const float4*)X)[v];
        float xs[4] = {x.x, x.y, x.z, x.w};
        unsigned short h[4], l[4];
        #pragma unroll
        for (int i = 0; i < 4; i++) {
            __nv_bfloat16 bh = __float2bfloat16(xs[i]);
            __nv_bfloat16 bl = __float2bfloat16(xs[i] - __bfloat162float(bh));
            h[i] = *(unsigned short*)&bh;
            l[i] = *(unsigned short*)&bl;
        }
        uint2 hv = make_uint2((uint32_t)h[0] | ((uint32_t)h[1] << 16),
                              (uint32_t)h[2] | ((uint32_t)h[3] << 16));
        uint2 lv = make_uint2((uint32_t)l[0] | ((uint32_t)l[1] << 16),
                              (uint32_t)l[2] | ((uint32_t)l[3] << 16));
        *(uint2*)(sm + r * LDA + k0)          = hv;
        *(uint2*)(sm + SM_ALO + r * LDA + k0) = lv;
    }

    float* Om[4] = {g_q, g_k, g_v, g_h};

    #pragma unroll
    for (int m = 0; m < 4; m++) {
        __syncthreads();
        const uint4* ghi = (const uint4*)(g_wt_hi + m * 128 * 128);
        const uint4* glo = (const uint4*)(g_wt_lo + m * 128 * 128);
        #pragma unroll
        for (int j = 0; j < 8; j++) {
            int idx = t + 256 * j;      // 0..2047 (uint4 = 8 bf16)
            int n = idx >> 4;
            int c = idx & 15;
            *(uint4*)(sm + SM_BHI + n * LDA + c * 8) = ghi[idx];
            *(uint4*)(sm + SM_BLO + n * LDA + c * 8) = glo[idx];
        }
        __syncthreads();

        wmma::fragment<wmma::accumulator, 16, 16, 16, float> acc[2][4];
        #pragma unroll
        for (int i = 0; i < 2; i++)
            #pragma unroll
            for (int j = 0; j < 4; j++)
                wmma::load_matrix_sync(acc[i][j],
                    g_btile + m * 16 * 128 + wn * 64 + j * 16, 128,
                    wmma::mem_row_major);

        #pragma unroll
        for (int ks = 0; ks < 8; ks++) {
            wmma::fragment<wmma::matrix_a, 16, 16, 16, __nv_bfloat16, wmma::row_major> ah[2], al[2];
            wmma::fragment<wmma::matrix_b, 16, 16, 16, __nv_bfloat16, wmma::col_major> bh[4], bl[4];
            #pragma unroll
            for (int i = 0; i < 2; i++) {
                int r = wm * 32 + i * 16;
                wmma::load_matrix_sync(ah[i], sm + r * LDA + ks * 16, LDA);
                wmma::load_matrix_sync(al[i], sm + SM_ALO + r * LDA + ks * 16, LDA);
            }
            #pragma unroll
            for (int j = 0; j < 4; j++) {
                int n = wn * 64 + j * 16;
                wmma::load_matrix_sync(bh[j], sm + SM_BHI + n * LDA + ks * 16, LDA);
                wmma::load_matrix_sync(bl[j], sm + SM_BLO + n * LDA + ks * 16, LDA);
            }
            #pragma unroll
            for (int i = 0; i < 2; i++)
                #pragma unroll
                for (int j = 0; j < 4; j++) {
                    wmma::mma_sync(acc[i][j], ah[i], bh[j], acc[i][j]);
                    wmma::mma_sync(acc[i][j], al[i], bh[j], acc[i][j]);
                    wmma::mma_sync(acc[i][j], ah[i], bl[j], acc[i][j]);
                }
        }

        float* O = Om[m] + (size_t)row0 * DIM;
        #pragma unroll
        for (int i = 0; i < 2; i++)
            #pragma unroll
            for (int j = 0; j < 4; j++)
                wmma::store_matrix_sync(
                    O + (size_t)(wm * 32 + i * 16) * DIM + wn * 64 + j * 16,
                    acc[i][j], DIM, wmma::mem_row_major);
    }
}

// ---------------- CSR build ----------------
__global__ void edge_hist(const int* __restrict__ eih, const int* __restrict__ eil)
{
    int e = blockIdx.x * 256 + threadIdx.x;
    if (e >= ET) return;
    int dst = (e < EHI) ? eih[EHI + e] : (eil[ELO + (e - EHI)] + NHI);
    atomicAdd(&g_dcnt[dst], 1);
}

// single-block exclusive scan over NT = 1024 * 260 counts
__global__ void scan_counts()
{
    __shared__ int ssum[1024];
    const int t = threadIdx.x;
    const int base = t * 260;
    int s = 0;
    for (int i = 0; i < 260; i++) s += g_dcnt[base + i];
    ssum[t] = s;
    __syncthreads();
    #pragma unroll
    for (int off = 1; off < 1024; off <<= 1) {
        int v = (t >= off) ? ssum[t - off] : 0;
        __syncthreads();
        ssum[t] += v;
        __syncthreads();
    }
    int run = ssum[t] - s;   // exclusive base for this chunk
    for (int i = 0; i < 260; i++) {
        g_rowptr[base + i] = run;
        g_cursor[base + i] = run;
        run += g_dcnt[base + i];
    }
    if (t == 1023) g_rowptr[NT] = run;
}

__global__ void edge_scatter(const int* __restrict__ eih, const int* __restrict__ eil)
{
    int e = blockIdx.x * 256 + threadIdx.x;
    if (e >= ET) return;
    int src, dst;
    if (e < EHI) { src = eih[e];             dst = eih[EHI + e]; }
    else         { src = eil[e - EHI] + NHI; dst = eil[ELO + (e - EHI)] + NHI; }
    int pos = atomicAdd(&g_cursor[dst], 1);
    g_col[pos] = src;
}

// ---------------- K2: one-pass attention (online softmax), one warp per node ----------------
__global__ void __launch_bounds__(256)
attn_node()
{
    int node = blockIdx.x * 8 + threadIdx.y;
    int lane = threadIdx.x;
    int s = g_rowptr[node];
    int e1 = g_rowptr[node + 1];
    if (s == e1) return;

    const float* qr = g_q + (size_t)node * DIM;
    float qv[NHEAD];
    #pragma unroll
    for (int h = 0; h < NHEAD; h++) qv[h] = qr[h * HDIM + lane];

    float m[NHEAD], d[NHEAD], acc[NHEAD];
    #pragma unroll
    for (int h = 0; h < NHEAD; h++) { m[h] = -INFINITY; d[h] = 0.f; acc[h] = 0.f; }

    for (int i = s; i < e1; i++) {
        int src = g_col[i];
        const float* kr = g_k + (size_t)src * DIM;
        const float* vr = g_v + (size_t)src * DIM;
        float kx[NHEAD], vx[NHEAD];
        #pragma unroll
        for (int h = 0; h < NHEAD; h++) kx[h] = kr[h * HDIM + lane];
        #pragma unroll
        for (int h = 0; h < NHEAD; h++) vx[h] = vr[h * HDIM + lane];
        #pragma unroll
        for (int h = 0; h < NHEAD; h++) {
            float sc = warp_sum(qv[h] * kx[h]) * SCALE;
            float mn = fmaxf(m[h], sc);
            float c = __expf(m[h] - mn);     // 0 when m was -inf
            float w = __expf(sc - mn);
            d[h] = d[h] * c + w;
            acc[h] = acc[h] * c + w * vx[h];
            m[h] = mn;
        }
    }
    float* hr = g_h + (size_t)node * DIM;
    #pragma unroll
    for (int h = 0; h < NHEAD; h++)
        hr[h * HDIM + lane] += acc[h] / d[h];
}

// ---------------- K3: LayerNorm + ReLU (in place) ----------------
__global__ void ln_relu(const float* __restrict__ lnw, const float* __restrict__ lnb)
{
    int node = blockIdx.x * 8 + threadIdx.y;
    int lane = threadIdx.x;
    float* row = g_h + (size_t)node * DIM;
    float4 v = ((float4*)row)[lane];
    float s = warp_sum(v.x + v.y + v.z + v.w);
    float sq = warp_sum(v.x * v.x + v.y * v.y + v.z * v.z + v.w * v.w);
    float mean = s * (1.0f / 128.0f);
    float var = sq * (1.0f / 128.0f) - mean * mean;
    float rstd = rsqrtf(var + 1e-5f);
    float4 w = ((const float4*)lnw)[lane];
    float4 b = ((const float4*)lnb)[lane];
    float4 o;
    o.x = fmaxf((v.x - mean) * rstd * w.x + b.x, 0.0f);
    o.y = fmaxf((v.y - mean) * rstd * w.y + b.y, 0.0f);
    o.z = fmaxf((v.z - mean) * rstd * w.z + b.z, 0.0f);
    o.w = fmaxf((v.w - mean) * rstd * w.w + b.w, 0.0f);
    ((float4*)row)[lane] = o;
}

// ---------------- K4: segmented pool + high-node gating (one warp per high node) ----------------
__device__ __forceinline__ int lower_bound_batch(const int* __restrict__ batch, int key)
{
    int lo = 0, hi = NLO;
    while (lo < hi) {
        int mid = (lo + hi) >> 1;
        if (batch[mid] < key) lo = mid + 1; else hi = mid;
    }
    return lo;
}

__global__ void __launch_bounds__(256)
pool_final_high(const int* __restrict__ batch, const float* __restrict__ wlh,
                float* __restrict__ out)
{
    int g = blockIdx.x * 8 + threadIdx.y;
    int lane = threadIdx.x;
    int lb = lower_bound_batch(batch, g);
    int ub = lower_bound_batch(batch, g + 1);

    float s[NHEAD] = {0.f, 0.f, 0.f, 0.f};
    for (int j = lb; j < ub; j++) {
        const float* lr = g_h + (size_t)(NHI + j) * DIM;
        #pragma unroll
        for (int h = 0; h < NHEAD; h++) s[h] += lr[h * HDIM + lane];
    }
    float inv = 1.0f / fmaxf((float)(ub - lb), 1.0f);
    float pv[NHEAD];
    #pragma unroll
    for (int h = 0; h < NHEAD; h++) pv[h] = s[h] * inv;

    const float* hrow = g_h + (size_t)g * DIM;
    float hv[NHEAD];
    #pragma unroll
    for (int h = 0; h < NHEAD; h++) hv[h] = hrow[h * HDIM + lane];

    float dot = 0.f;
    #pragma unroll
    for (int h = 0; h < NHEAD; h++)
        dot += hv[h] * wlh[h * HDIM + lane] + pv[h] * wlh[DIM + h * HDIM + lane];
    dot = warp_sum(dot);
    float sgm = 1.0f / (1.0f + __expf(-dot));
    float* O = out + (size_t)g * DIM;
    #pragma unroll
    for (int h = 0; h < NHEAD; h++)
        O[h * HDIM + lane] = sgm * hv[h] + (1.0f - sgm) * pv[h];
}

// ---------------- K5: low-node gating epilogue ----------------
__global__ void final_low(const float* __restrict__ whl, const int* __restrict__ batch,
                          float* __restrict__ out)
{
    int j = blockIdx.x * 8 + threadIdx.y;
    int lane = threadIdx.x;
    int g = batch[j];
    float4 hb = ((const float4*)(g_h + (size_t)g * DIM))[lane];
    float4 lv = ((const float4*)(g_h + (size_t)(NHI + j) * DIM))[lane];
    float4 w0 = ((const float4*)whl)[lane];
    float4 w1 = ((const float4*)(whl + DIM))[lane];
    float d = hb.x * w0.x + hb.y * w0.y + hb.z * w0.z + hb.w * w0.w
            + lv.x * w1.x + lv.y * w1.y + lv.z * w1.z + lv.w * w1.w;
    d = warp_sum(d);
    float a = 1.0f / (1.0f + __expf(-d));
    float4 o;
    o.x = a * lv.x + (1.0f - a) * hb.x;
    o.y = a * lv.y + (1.0f - a) * hb.y;
    o.z = a * lv.z + (1.0f - a) * hb.z;
    o.w = a * lv.w + (1.0f - a) * hb.w;
    ((float4*)(out + (size_t)j * DIM))[lane] = o;
}

// ---------------- launch ----------------
extern "C" void kernel_launch(void* const* d_in, const int* in_sizes, int n_in,
                              void* d_out, int out_size)
{
    const float* high_emb = (const float*)d_in[0];
    const float* low_emb  = (const float*)d_in[1];
    const float* Wq = (const float*)d_in[2];  const float* bq = (const float*)d_in[3];
    const float* Wk = (const float*)d_in[4];  const float* bk = (const float*)d_in[5];
    const float* Wv = (const float*)d_in[6];  const float* bv = (const float*)d_in[7];
    const float* Ws = (const float*)d_in[8];  const float* bs = (const float*)d_in[9];
    const float* lnw = (const float*)d_in[10];
    const float* lnb = (const float*)d_in[11];
    const float* wlh = (const float*)d_in[12];
    const float* whl = (const float*)d_in[13];
    const int* eih   = (const int*)d_in[14];
    const int* eil   = (const int*)d_in[15];
    const int* batch = (const int*)d_in[16];
    float* out = (float*)d_out;

    void* pcnt;
    cudaGetSymbolAddress(&pcnt, g_dcnt);
    cudaMemsetAsync(pcnt, 0, NT * sizeof(int), 0);

    cudaFuncSetAttribute(gemm_hmma, cudaFuncAttributeMaxDynamicSharedMemorySize, SM_BYTES);

    prep_w<<<256, 256>>>(Wq, Wk, Wv, Ws);
    prep_b<<<32, 256>>>(bq, bk, bv, bs);

    // CSR build (independent of GEMM)
    edge_hist<<<(ET + 255) / 256, 256>>>(eih, eil);
    scan_counts<<<1, 1024>>>();
    edge_scatter<<<(ET + 255) / 256, 256>>>(eih, eil);

    gemm_hmma<<<NT / 128, 256, SM_BYTES>>>(high_emb, low_emb);

    dim3 t32x8(32, 8);
    attn_node<<<NT / 8, t32x8>>>();
    ln_relu<<<NT / 8, t32x8>>>(lnw, lnb);
    pool_final_high<<<NHI / 8, t32x8>>>(batch, wlh, out);
    final_low<<<NLO / 8, t32x8>>>(whl, batch, out + (size_t)NHI * DIM);
}

// round 5
// speedup vs baseline: 1.0884x; 1.0884x over previous
#include <cuda_runtime.h>
#include <cuda_bf16.h>
#include <mma.h>
#include <math.h>
#include <cstdint>

using namespace nvcuda;

#define NHI 4096
#define NLO 262144
#define NT  (NHI + NLO)      /* 266240 = 260 * 1024 */
#define EHI 65536
#define ELO 524288
#define ET  (EHI + ELO)
#define DIM 128
#define NHEAD 4
#define HDIM 32
#define SCALE 0.17677669529663687f   /* 1/sqrt(32) */
#define NBLK 260             /* scan blocks */

// ---------------- scratch (device globals; no allocation allowed) ----------------
__device__ float g_q[(size_t)NT * DIM];
__device__ float g_k[(size_t)NT * DIM];
__device__ float g_v[(size_t)NT * DIM];
__device__ float g_h[(size_t)NT * DIM];      // skip -> += agg -> LN+relu in place
__device__ int g_dcnt[NT];
__device__ int g_rowptr[NT + 1];
__device__ int g_cursor[NT];
__device__ int g_col[ET];
__device__ int g_bsum[NBLK];
__device__ int g_bex[NBLK];
// W^T bf16 hi/lo images: [matrix 0..3][n 0..127][k 0..127]
__device__ __align__(16) __nv_bfloat16 g_wt_hi[4 * 128 * 128];
__device__ __align__(16) __nv_bfloat16 g_wt_lo[4 * 128 * 128];
// bias broadcast tiles: [matrix][16 rows][128 cols] (all rows identical)
__device__ __align__(16) float g_btile[4 * 16 * 128];

// ---------------- helpers ----------------
__device__ __forceinline__ float warp_sum(float v) {
    #pragma unroll
    for (int o = 16; o; o >>= 1) v += __shfl_xor_sync(0xffffffffu, v, o);
    return v;
}

// ---------------- K0a: prep weights -> W^T bf16 hi/lo ----------------
__global__ void prep_w(const float* __restrict__ Wq, const float* __restrict__ Wk,
                       const float* __restrict__ Wv, const float* __restrict__ Ws)
{
    int idx = blockIdx.x * 256 + threadIdx.x;  // 0..65535
    int m = idx >> 14;       // matrix 0..3
    int n = (idx >> 7) & 127;
    int k = idx & 127;
    const float* W = (m == 0) ? Wq : (m == 1) ? Wk : (m == 2) ? Wv : Ws;
    float w = W[k * 128 + n];
    __nv_bfloat16 hi = __float2bfloat16(w);
    __nv_bfloat16 lo = __float2bfloat16(w - __bfloat162float(hi));
    g_wt_hi[idx] = hi;
    g_wt_lo[idx] = lo;
}

// ---------------- K0b: prep bias tiles ----------------
__global__ void prep_b(const float* __restrict__ bq, const float* __restrict__ bk,
                       const float* __restrict__ bv, const float* __restrict__ bs)
{
    int idx = blockIdx.x * 256 + threadIdx.x;  // 0..8191
    int m = idx >> 11;
    int n = idx & 127;
    const float* B = (m == 0) ? bq : (m == 1) ? bk : (m == 2) ? bv : bs;
    g_btile[idx] = B[n];
}

// ---------------- K1: fused QKV+skip GEMM via HMMA (bf16x3 split) ----------------
#define LDA 136
#define SM_ALO (128 * LDA)
#define SM_BHI (2 * 128 * LDA)
#define SM_BLO (3 * 128 * LDA)
#define SM_BYTES (4 * 128 * LDA * 2)

__global__ void __launch_bounds__(256, 1)
gemm_hmma(const float* __restrict__ xh, const float* __restrict__ xl)
{
    extern __shared__ __nv_bfloat16 sm[];
    const int t = threadIdx.x;
    const int wid = t >> 5;
    const int wm = wid & 3;        // warp row group: 32 rows each
    const int wn = wid >> 2;       // warp col group: 64 cols each

    const int row0 = blockIdx.x * 128;
    const float* X = (row0 < NHI) ? (xh + (size_t)row0 * DIM)
                                  : (xl + (size_t)(row0 - NHI) * DIM);
    #pragma unroll
    for (int j = 0; j < 16; j++) {
        int v = t + 256 * j;            // float4 index 0..4095
        int r = v >> 5;                 // row 0..127
        int k0 = (v & 31) * 4;          // k 0..124
        float4 x = ((const float4*)X)[v];
        float xs[4] = {x.x, x.y, x.z, x.w};
        unsigned short h[4], l[4];
        #pragma unroll
        for (int i = 0; i < 4; i++) {
            __nv_bfloat16 bh = __float2bfloat16(xs[i]);
            __nv_bfloat16 bl = __float2bfloat16(xs[i] - __bfloat162float(bh));
            h[i] = *(unsigned short*)&bh;
            l[i] = *(unsigned short*)&bl;
        }
        uint2 hv = make_uint2((uint32_t)h[0] | ((uint32_t)h[1] << 16),
                              (uint32_t)h[2] | ((uint32_t)h[3] << 16));
        uint2 lv = make_uint2((uint32_t)l[0] | ((uint32_t)l[1] << 16),
                              (uint32_t)l[2] | ((uint32_t)l[3] << 16));
        *(uint2*)(sm + r * LDA + k0)          = hv;
        *(uint2*)(sm + SM_ALO + r * LDA + k0) = lv;
    }

    float* Om[4] = {g_q, g_k, g_v, g_h};

    #pragma unroll
    for (int m = 0; m < 4; m++) {
        __syncthreads();
        const uint4* ghi = (const uint4*)(g_wt_hi + m * 128 * 128);
        const uint4* glo = (const uint4*)(g_wt_lo + m * 128 * 128);
        #pragma unroll
        for (int j = 0; j < 8; j++) {
            int idx = t + 256 * j;      // 0..2047 (uint4 = 8 bf16)
            int n = idx >> 4;
            int c = idx & 15;
            *(uint4*)(sm + SM_BHI + n * LDA + c * 8) = ghi[idx];
            *(uint4*)(sm + SM_BLO + n * LDA + c * 8) = glo[idx];
        }
        __syncthreads();

        wmma::fragment<wmma::accumulator, 16, 16, 16, float> acc[2][4];
        #pragma unroll
        for (int i = 0; i < 2; i++)
            #pragma unroll
            for (int j = 0; j < 4; j++)
                wmma::load_matrix_sync(acc[i][j],
                    g_btile + m * 16 * 128 + wn * 64 + j * 16, 128,
                    wmma::mem_row_major);

        #pragma unroll
        for (int ks = 0; ks < 8; ks++) {
            wmma::fragment<wmma::matrix_a, 16, 16, 16, __nv_bfloat16, wmma::row_major> ah[2], al[2];
            wmma::fragment<wmma::matrix_b, 16, 16, 16, __nv_bfloat16, wmma::col_major> bh[4], bl[4];
            #pragma unroll
            for (int i = 0; i < 2; i++) {
                int r = wm * 32 + i * 16;
                wmma::load_matrix_sync(ah[i], sm + r * LDA + ks * 16, LDA);
                wmma::load_matrix_sync(al[i], sm + SM_ALO + r * LDA + ks * 16, LDA);
            }
            #pragma unroll
            for (int j = 0; j < 4; j++) {
                int n = wn * 64 + j * 16;
                wmma::load_matrix_sync(bh[j], sm + SM_BHI + n * LDA + ks * 16, LDA);
                wmma::load_matrix_sync(bl[j], sm + SM_BLO + n * LDA + ks * 16, LDA);
            }
            #pragma unroll
            for (int i = 0; i < 2; i++)
                #pragma unroll
                for (int j = 0; j < 4; j++) {
                    wmma::mma_sync(acc[i][j], ah[i], bh[j], acc[i][j]);
                    wmma::mma_sync(acc[i][j], al[i], bh[j], acc[i][j]);
                    wmma::mma_sync(acc[i][j], ah[i], bl[j], acc[i][j]);
                }
        }

        float* O = Om[m] + (size_t)row0 * DIM;
        #pragma unroll
        for (int i = 0; i < 2; i++)
            #pragma unroll
            for (int j = 0; j < 4; j++)
                wmma::store_matrix_sync(
                    O + (size_t)(wm * 32 + i * 16) * DIM + wn * 64 + j * 16,
                    acc[i][j], DIM, wmma::mem_row_major);
    }
}

// ---------------- CSR build ----------------
__global__ void edge_hist(const int* __restrict__ eih, const int* __restrict__ eil)
{
    int e = blockIdx.x * 256 + threadIdx.x;
    if (e >= ET) return;
    int dst = (e < EHI) ? eih[EHI + e] : (eil[ELO + (e - EHI)] + NHI);
    atomicAdd(&g_dcnt[dst], 1);
}

// parallel exclusive scan: 260 blocks x 1024 (local), then block sums, then add
__global__ void scan_local()
{
    __shared__ int sh[1024];
    const int t = threadIdx.x;
    const int i = blockIdx.x * 1024 + t;
    int v = g_dcnt[i];
    sh[t] = v;
    __syncthreads();
    #pragma unroll
    for (int off = 1; off < 1024; off <<= 1) {
        int u = (t >= off) ? sh[t - off] : 0;
        __syncthreads();
        sh[t] += u;
        __syncthreads();
    }
    g_rowptr[i] = sh[t] - v;            // local exclusive
    if (t == 1023) g_bsum[blockIdx.x] = sh[t];
}

__global__ void scan_bsum()
{
    __shared__ int sh[512];
    const int t = threadIdx.x;          // 512 threads
    int v = (t < NBLK) ? g_bsum[t] : 0;
    sh[t] = v;
    __syncthreads();
    #pragma unroll
    for (int off = 1; off < 512; off <<= 1) {
        int u = (t >= off) ? sh[t - off] : 0;
        __syncthreads();
        sh[t] += u;
        __syncthreads();
    }
    if (t < NBLK) g_bex[t] = sh[t] - v; // exclusive block base
    if (t == 511) g_rowptr[NT] = sh[511];
}

__global__ void scan_add()
{
    const int i = blockIdx.x * 1024 + threadIdx.x;
    int r = g_rowptr[i] + g_bex[blockIdx.x];
    g_rowptr[i] = r;
    g_cursor[i] = r;
}

__global__ void edge_scatter(const int* __restrict__ eih, const int* __restrict__ eil)
{
    int e = blockIdx.x * 256 + threadIdx.x;
    if (e >= ET) return;
    int src, dst;
    if (e < EHI) { src = eih[e];             dst = eih[EHI + e]; }
    else         { src = eil[e - EHI] + NHI; dst = eil[ELO + (e - EHI)] + NHI; }
    int pos = atomicAdd(&g_cursor[dst], 1);
    g_col[pos] = src;
}

// ---------------- K2: one-pass attention (online softmax), one warp per node ----------------
__global__ void __launch_bounds__(256)
attn_node()
{
    int node = blockIdx.x * 8 + threadIdx.y;
    int lane = threadIdx.x;
    int s = g_rowptr[node];
    int e1 = g_rowptr[node + 1];
    if (s == e1) return;

    const float* qr = g_q + (size_t)node * DIM;
    float qv[NHEAD];
    #pragma unroll
    for (int h = 0; h < NHEAD; h++) qv[h] = qr[h * HDIM + lane];

    float m[NHEAD], d[NHEAD], acc[NHEAD];
    #pragma unroll
    for (int h = 0; h < NHEAD; h++) { m[h] = -INFINITY; d[h] = 0.f; acc[h] = 0.f; }

    for (int i = s; i < e1; i++) {
        int src = g_col[i];
        const float* kr = g_k + (size_t)src * DIM;
        const float* vr = g_v + (size_t)src * DIM;
        float kx[NHEAD], vx[NHEAD];
        #pragma unroll
        for (int h = 0; h < NHEAD; h++) kx[h] = kr[h * HDIM + lane];
        #pragma unroll
        for (int h = 0; h < NHEAD; h++) vx[h] = vr[h * HDIM + lane];
        #pragma unroll
        for (int h = 0; h < NHEAD; h++) {
            float sc = warp_sum(qv[h] * kx[h]) * SCALE;
            float mn = fmaxf(m[h], sc);
            float c = __expf(m[h] - mn);     // 0 when m was -inf
            float w = __expf(sc - mn);
            d[h] = d[h] * c + w;
            acc[h] = acc[h] * c + w * vx[h];
            m[h] = mn;
        }
    }
    float* hr = g_h + (size_t)node * DIM;
    #pragma unroll
    for (int h = 0; h < NHEAD; h++)
        hr[h * HDIM + lane] += acc[h] / d[h];
}

// ---------------- K3: LayerNorm + ReLU (in place) ----------------
__global__ void ln_relu(const float* __restrict__ lnw, const float* __restrict__ lnb)
{
    int node = blockIdx.x * 8 + threadIdx.y;
    int lane = threadIdx.x;
    float* row = g_h + (size_t)node * DIM;
    float4 v = ((float4*)row)[lane];
    float s = warp_sum(v.x + v.y + v.z + v.w);
    float sq = warp_sum(v.x * v.x + v.y * v.y + v.z * v.z + v.w * v.w);
    float mean = s * (1.0f / 128.0f);
    float var = sq * (1.0f / 128.0f) - mean * mean;
    float rstd = rsqrtf(var + 1e-5f);
    float4 w = ((const float4*)lnw)[lane];
    float4 b = ((const float4*)lnb)[lane];
    float4 o;
    o.x = fmaxf((v.x - mean) * rstd * w.x + b.x, 0.0f);
    o.y = fmaxf((v.y - mean) * rstd * w.y + b.y, 0.0f);
    o.z = fmaxf((v.z - mean) * rstd * w.z + b.z, 0.0f);
    o.w = fmaxf((v.w - mean) * rstd * w.w + b.w, 0.0f);
    ((float4*)row)[lane] = o;
}

// ---------------- K4: segmented pool + high-node gating (one warp per high node) ----------------
__device__ __forceinline__ int lower_bound_batch(const int* __restrict__ batch, int key)
{
    int lo = 0, hi = NLO;
    while (lo < hi) {
        int mid = (lo + hi) >> 1;
        if (batch[mid] < key) lo = mid + 1; else hi = mid;
    }
    return lo;
}

__global__ void __launch_bounds__(256)
pool_final_high(const int* __restrict__ batch, const float* __restrict__ wlh,
                float* __restrict__ out)
{
    int g = blockIdx.x * 8 + threadIdx.y;
    int lane = threadIdx.x;
    int lb = lower_bound_batch(batch, g);
    int ub = lower_bound_batch(batch, g + 1);

    float s[NHEAD] = {0.f, 0.f, 0.f, 0.f};
    for (int j = lb; j < ub; j++) {
        const float* lr = g_h + (size_t)(NHI + j) * DIM;
        #pragma unroll
        for (int h = 0; h < NHEAD; h++) s[h] += lr[h * HDIM + lane];
    }
    float inv = 1.0f / fmaxf((float)(ub - lb), 1.0f);
    float pv[NHEAD];
    #pragma unroll
    for (int h = 0; h < NHEAD; h++) pv[h] = s[h] * inv;

    const float* hrow = g_h + (size_t)g * DIM;
    float hv[NHEAD];
    #pragma unroll
    for (int h = 0; h < NHEAD; h++) hv[h] = hrow[h * HDIM + lane];

    float dot = 0.f;
    #pragma unroll
    for (int h = 0; h < NHEAD; h++)
        dot += hv[h] * wlh[h * HDIM + lane] + pv[h] * wlh[DIM + h * HDIM + lane];
    dot = warp_sum(dot);
    float sgm = 1.0f / (1.0f + __expf(-dot));
    float* O = out + (size_t)g * DIM;
    #pragma unroll
    for (int h = 0; h < NHEAD; h++)
        O[h * HDIM + lane] = sgm * hv[h] + (1.0f - sgm) * pv[h];
}

// ---------------- K5: low-node gating epilogue ----------------
__global__ void final_low(const float* __restrict__ whl, const int* __restrict__ batch,
                          float* __restrict__ out)
{
    int j = blockIdx.x * 8 + threadIdx.y;
    int lane = threadIdx.x;
    int g = batch[j];
    float4 hb = ((const float4*)(g_h + (size_t)g * DIM))[lane];
    float4 lv = ((const float4*)(g_h + (size_t)(NHI + j) * DIM))[lane];
    float4 w0 = ((const float4*)whl)[lane];
    float4 w1 = ((const float4*)(whl + DIM))[lane];
    float d = hb.x * w0.x + hb.y * w0.y + hb.z * w0.z + hb.w * w0.w
            + lv.x * w1.x + lv.y * w1.y + lv.z * w1.z + lv.w * w1.w;
    d = warp_sum(d);
    float a = 1.0f / (1.0f + __expf(-d));
    float4 o;
    o.x = a * lv.x + (1.0f - a) * hb.x;
    o.y = a * lv.y + (1.0f - a) * hb.y;
    o.z = a * lv.z + (1.0f - a) * hb.z;
    o.w = a * lv.w + (1.0f - a) * hb.w;
    ((float4*)(out + (size_t)j * DIM))[lane] = o;
}

// ---------------- launch ----------------
extern "C" void kernel_launch(void* const* d_in, const int* in_sizes, int n_in,
                              void* d_out, int out_size)
{
    const float* high_emb = (const float*)d_in[0];
    const float* low_emb  = (const float*)d_in[1];
    const float* Wq = (const float*)d_in[2];  const float* bq = (const float*)d_in[3];
    const float* Wk = (const float*)d_in[4];  const float* bk = (const float*)d_in[5];
    const float* Wv = (const float*)d_in[6];  const float* bv = (const float*)d_in[7];
    const float* Ws = (const float*)d_in[8];  const float* bs = (const float*)d_in[9];
    const float* lnw = (const float*)d_in[10];
    const float* lnb = (const float*)d_in[11];
    const float* wlh = (const float*)d_in[12];
    const float* whl = (const float*)d_in[13];
    const int* eih   = (const int*)d_in[14];
    const int* eil   = (const int*)d_in[15];
    const int* batch = (const int*)d_in[16];
    float* out = (float*)d_out;

    void* pcnt;
    cudaGetSymbolAddress(&pcnt, g_dcnt);
    cudaMemsetAsync(pcnt, 0, NT * sizeof(int), 0);

    cudaFuncSetAttribute(gemm_hmma, cudaFuncAttributeMaxDynamicSharedMemorySize, SM_BYTES);

    prep_w<<<256, 256>>>(Wq, Wk, Wv, Ws);
    prep_b<<<32, 256>>>(bq, bk, bv, bs);

    // CSR build (independent of GEMM)
    edge_hist<<<(ET + 255) / 256, 256>>>(eih, eil);
    scan_local<<<NBLK, 1024>>>();
    scan_bsum<<<1, 512>>>();
    scan_add<<<NBLK, 1024>>>();
    edge_scatter<<<(ET + 255) / 256, 256>>>(eih, eil);

    gemm_hmma<<<NT / 128, 256, SM_BYTES>>>(high_emb, low_emb);

    dim3 t32x8(32, 8);
    attn_node<<<NT / 8, t32x8>>>();
    ln_relu<<<NT / 8, t32x8>>>(lnw, lnb);
    pool_final_high<<<NHI / 8, t32x8>>>(batch, wlh, out);
    final_low<<<NLO / 8, t32x8>>>(whl, batch, out + (size_t)NHI * DIM);
}

// round 6
// speedup vs baseline: 1.6938x; 1.5562x over previous
#include <cuda_runtime.h>
#include <cuda_bf16.h>
#include <mma.h>
#include <math.h>
#include <cstdint>

using namespace nvcuda;

#define NHI 4096
#define NLO 262144
#define NT  (NHI + NLO)      /* 266240 = 260 * 1024 */
#define EHI 65536
#define ELO 524288
#define ET  (EHI + ELO)
#define DIM 128
#define NHEAD 4
#define HDIM 32
#define SCALE 0.17677669529663687f   /* 1/sqrt(32) */
#define NBLK 260             /* scan blocks */

// ---------------- scratch (device globals; no allocation allowed) ----------------
__device__ float g_q[(size_t)NT * DIM];
__device__ float g_k[(size_t)NT * DIM];
__device__ float g_v[(size_t)NT * DIM];
__device__ float g_h[(size_t)NT * DIM];      // skip -> +agg+LN+relu in place
__device__ int g_dcnt[NT];
__device__ int g_rowptr[NT + 1];
__device__ int g_cursor[NT];
__device__ int g_col[ET];
__device__ int g_bsum[NBLK];
__device__ int g_bex[NBLK];
// W^T bf16 hi/lo images: [matrix 0..3][n 0..127][k 0..127]
__device__ __align__(16) __nv_bfloat16 g_wt_hi[4 * 128 * 128];
__device__ __align__(16) __nv_bfloat16 g_wt_lo[4 * 128 * 128];
// bias broadcast tiles: [matrix][16 rows][128 cols] (all rows identical)
__device__ __align__(16) float g_btile[4 * 16 * 128];

// ---------------- helpers ----------------
__device__ __forceinline__ float warp_sum(float v) {
    #pragma unroll
    for (int o = 16; o; o >>= 1) v += __shfl_xor_sync(0xffffffffu, v, o);
    return v;
}
__device__ __forceinline__ uint32_t smem_u32(const void* p) {
    uint32_t a;
    asm("{ .reg .u64 t; cvta.to.shared.u64 t, %1; cvt.u32.u64 %0, t; }"
        : "=r"(a) : "l"(p));
    return a;
}
__device__ __forceinline__ void cp_async16(uint32_t dst, const void* src) {
    asm volatile("cp.async.cg.shared.global [%0], [%1], 16;" :: "r"(dst), "l"(src));
}

// ---------------- K0a: prep weights -> W^T bf16 hi/lo ----------------
__global__ void prep_w(const float* __restrict__ Wq, const float* __restrict__ Wk,
                       const float* __restrict__ Wv, const float* __restrict__ Ws)
{
    int idx = blockIdx.x * 256 + threadIdx.x;  // 0..65535
    int m = idx >> 14;       // matrix 0..3
    int n = (idx >> 7) & 127;
    int k = idx & 127;
    const float* W = (m == 0) ? Wq : (m == 1) ? Wk : (m == 2) ? Wv : Ws;
    float w = W[k * 128 + n];
    __nv_bfloat16 hi = __float2bfloat16(w);
    __nv_bfloat16 lo = __float2bfloat16(w - __bfloat162float(hi));
    g_wt_hi[idx] = hi;
    g_wt_lo[idx] = lo;
}

// ---------------- K0b: prep bias tiles ----------------
__global__ void prep_b(const float* __restrict__ bq, const float* __restrict__ bk,
                       const float* __restrict__ bv, const float* __restrict__ bs)
{
    int idx = blockIdx.x * 256 + threadIdx.x;  // 0..8191
    int m = idx >> 11;
    int n = idx & 127;
    const float* B = (m == 0) ? bq : (m == 1) ? bk : (m == 2) ? bv : bs;
    g_btile[idx] = B[n];
}

// ---------------- K1: fused QKV+skip GEMM via HMMA (bf16x3, cp.async pipelined B) ----------------
// SMEM (bf16 elements): A_hi[128*136], A_lo[128*136], Bbuf0{hi,lo}[2*128*136], Bbuf1{hi,lo}
#define LDA 136
#define A_ELEMS (128 * LDA)            /* 17408 */
#define SM_ALO  A_ELEMS
#define SM_B0   (2 * A_ELEMS)          /* 34816 */
#define SM_B1   (SM_B0 + 2 * A_ELEMS)  /* 69632 */
#define SM_BYTES (2 * (SM_B1 + 2 * A_ELEMS))  /* 104448 elems * 2B = 208896 */

__global__ void __launch_bounds__(256, 1)
gemm_hmma(const float* __restrict__ xh, const float* __restrict__ xl)
{
    extern __shared__ __nv_bfloat16 sm[];
    const uint32_t sbase = smem_u32(sm);
    const int t = threadIdx.x;
    const int wid = t >> 5;
    const int wm = wid & 3;        // warp row group: 32 rows each
    const int wn = wid >> 2;       // warp col group: 64 cols each

    // issue B prefetch for m=0 into buf0 (before A conversion, to overlap)
    {
        const uint4* ghi = (const uint4*)(g_wt_hi);
        const uint4* glo = (const uint4*)(g_wt_lo);
        uint32_t bhi = sbase + SM_B0 * 2;
        uint32_t blo = sbase + (SM_B0 + A_ELEMS) * 2;
        #pragma unroll
        for (int j = 0; j < 8; j++) {
            int idx = t + 256 * j;      // 0..2047 (16B chunks)
            int n = idx >> 4;
            int c = idx & 15;
            uint32_t off = (uint32_t)(n * LDA + c * 8) * 2;
            cp_async16(bhi + off, ghi + idx);
            cp_async16(blo + off, glo + idx);
        }
        asm volatile("cp.async.commit_group;");
    }

    // ---- load + split-convert A tile (128 rows x 128 k) ----
    const int row0 = blockIdx.x * 128;
    const float* X = (row0 < NHI) ? (xh + (size_t)row0 * DIM)
                                  : (xl + (size_t)(row0 - NHI) * DIM);
    #pragma unroll
    for (int j = 0; j < 16; j++) {
        int v = t + 256 * j;            // float4 index 0..4095
        int r = v >> 5;                 // row 0..127
        int k0 = (v & 31) * 4;          // k 0..124
        float4 x = ((const float4*)X)[v];
        float xs[4] = {x.x, x.y, x.z, x.w};
        unsigned short h[4], l[4];
        #pragma unroll
        for (int i = 0; i < 4; i++) {
            __nv_bfloat16 bh = __float2bfloat16(xs[i]);
            __nv_bfloat16 bl = __float2bfloat16(xs[i] - __bfloat162float(bh));
            h[i] = *(unsigned short*)&bh;
            l[i] = *(unsigned short*)&bl;
        }
        uint2 hv = make_uint2((uint32_t)h[0] | ((uint32_t)h[1] << 16),
                              (uint32_t)h[2] | ((uint32_t)h[3] << 16));
        uint2 lv = make_uint2((uint32_t)l[0] | ((uint32_t)l[1] << 16),
                              (uint32_t)l[2] | ((uint32_t)l[3] << 16));
        *(uint2*)(sm + r * LDA + k0)          = hv;
        *(uint2*)(sm + SM_ALO + r * LDA + k0) = lv;
    }

    float* Om[4] = {g_q, g_k, g_v, g_h};

    #pragma unroll
    for (int m = 0; m < 4; m++) {
        // issue prefetch for m+1 into the other buffer
        if (m < 3) {
            const uint4* ghi = (const uint4*)(g_wt_hi + (m + 1) * 128 * 128);
            const uint4* glo = (const uint4*)(g_wt_lo + (m + 1) * 128 * 128);
            int bsel = (m + 1) & 1;
            uint32_t bhi = sbase + (bsel ? SM_B1 : SM_B0) * 2;
            uint32_t blo = bhi + A_ELEMS * 2;
            #pragma unroll
            for (int j = 0; j < 8; j++) {
                int idx = t + 256 * j;
                int n = idx >> 4;
                int c = idx & 15;
                uint32_t off = (uint32_t)(n * LDA + c * 8) * 2;
                cp_async16(bhi + off, ghi + idx);
                cp_async16(blo + off, glo + idx);
            }
            asm volatile("cp.async.commit_group;");
            asm volatile("cp.async.wait_group 1;");
        } else {
            asm volatile("cp.async.wait_group 0;");
        }
        __syncthreads();   // B[m] ready; prior phase readers done (end-of-phase sync)

        const __nv_bfloat16* Bhi = sm + ((m & 1) ? SM_B1 : SM_B0);
        const __nv_bfloat16* Blo = Bhi + A_ELEMS;

        wmma::fragment<wmma::accumulator, 16, 16, 16, float> acc[2][4];
        #pragma unroll
        for (int i = 0; i < 2; i++)
            #pragma unroll
            for (int j = 0; j < 4; j++)
                wmma::load_matrix_sync(acc[i][j],
                    g_btile + m * 16 * 128 + wn * 64 + j * 16, 128,
                    wmma::mem_row_major);

        #pragma unroll
        for (int ks = 0; ks < 8; ks++) {
            wmma::fragment<wmma::matrix_a, 16, 16, 16, __nv_bfloat16, wmma::row_major> ah[2], al[2];
            wmma::fragment<wmma::matrix_b, 16, 16, 16, __nv_bfloat16, wmma::col_major> bh[4], bl[4];
            #pragma unroll
            for (int i = 0; i < 2; i++) {
                int r = wm * 32 + i * 16;
                wmma::load_matrix_sync(ah[i], sm + r * LDA + ks * 16, LDA);
                wmma::load_matrix_sync(al[i], sm + SM_ALO + r * LDA + ks * 16, LDA);
            }
            #pragma unroll
            for (int j = 0; j < 4; j++) {
                int n = wn * 64 + j * 16;
                wmma::load_matrix_sync(bh[j], Bhi + n * LDA + ks * 16, LDA);
                wmma::load_matrix_sync(bl[j], Blo + n * LDA + ks * 16, LDA);
            }
            #pragma unroll
            for (int i = 0; i < 2; i++)
                #pragma unroll
                for (int j = 0; j < 4; j++) {
                    wmma::mma_sync(acc[i][j], ah[i], bh[j], acc[i][j]);
                    wmma::mma_sync(acc[i][j], al[i], bh[j], acc[i][j]);
                    wmma::mma_sync(acc[i][j], ah[i], bl[j], acc[i][j]);
                }
        }

        float* O = Om[m] + (size_t)row0 * DIM;
        #pragma unroll
        for (int i = 0; i < 2; i++)
            #pragma unroll
            for (int j = 0; j < 4; j++)
                wmma::store_matrix_sync(
                    O + (size_t)(wm * 32 + i * 16) * DIM + wn * 64 + j * 16,
                    acc[i][j], DIM, wmma::mem_row_major);
        __syncthreads();   // all warps done reading B[m] before its buffer is refilled
    }
}

// ---------------- CSR build ----------------
__global__ void edge_hist(const int* __restrict__ eih, const int* __restrict__ eil)
{
    int e = blockIdx.x * 256 + threadIdx.x;
    if (e >= ET) return;
    int dst = (e < EHI) ? eih[EHI + e] : (eil[ELO + (e - EHI)] + NHI);
    atomicAdd(&g_dcnt[dst], 1);
}

__global__ void scan_local()
{
    __shared__ int sh[1024];
    const int t = threadIdx.x;
    const int i = blockIdx.x * 1024 + t;
    int v = g_dcnt[i];
    sh[t] = v;
    __syncthreads();
    #pragma unroll
    for (int off = 1; off < 1024; off <<= 1) {
        int u = (t >= off) ? sh[t - off] : 0;
        __syncthreads();
        sh[t] += u;
        __syncthreads();
    }
    g_rowptr[i] = sh[t] - v;            // local exclusive
    if (t == 1023) g_bsum[blockIdx.x] = sh[t];
}

__global__ void scan_bsum()
{
    __shared__ int sh[512];
    const int t = threadIdx.x;          // 512 threads
    int v = (t < NBLK) ? g_bsum[t] : 0;
    sh[t] = v;
    __syncthreads();
    #pragma unroll
    for (int off = 1; off < 512; off <<= 1) {
        int u = (t >= off) ? sh[t - off] : 0;
        __syncthreads();
        sh[t] += u;
        __syncthreads();
    }
    if (t < NBLK) g_bex[t] = sh[t] - v; // exclusive block base
    if (t == 511) g_rowptr[NT] = sh[511];
}

__global__ void scan_add()
{
    const int i = blockIdx.x * 1024 + threadIdx.x;
    int r = g_rowptr[i] + g_bex[blockIdx.x];
    g_rowptr[i] = r;
    g_cursor[i] = r;
}

__global__ void edge_scatter(const int* __restrict__ eih, const int* __restrict__ eil)
{
    int e = blockIdx.x * 256 + threadIdx.x;
    if (e >= ET) return;
    int src, dst;
    if (e < EHI) { src = eih[e];             dst = eih[EHI + e]; }
    else         { src = eil[e - EHI] + NHI; dst = eil[ELO + (e - EHI)] + NHI; }
    int pos = atomicAdd(&g_cursor[dst], 1);
    g_col[pos] = src;
}

// ---------------- K2: one-pass attention (online softmax) + fused LN/ReLU ----------------
__global__ void __launch_bounds__(256)
attn_ln(const float* __restrict__ lnw, const float* __restrict__ lnb)
{
    int node = blockIdx.x * 8 + threadIdx.y;
    int lane = threadIdx.x;
    int s = g_rowptr[node];
    int e1 = g_rowptr[node + 1];

    float val[NHEAD];
    float* hr = g_h + (size_t)node * DIM;
    #pragma unroll
    for (int h = 0; h < NHEAD; h++) val[h] = hr[h * HDIM + lane];  // skip term

    if (s < e1) {
        const float* qr = g_q + (size_t)node * DIM;
        float qv[NHEAD];
        #pragma unroll
        for (int h = 0; h < NHEAD; h++) qv[h] = qr[h * HDIM + lane];

        float m[NHEAD], d[NHEAD], acc[NHEAD];
        #pragma unroll
        for (int h = 0; h < NHEAD; h++) { m[h] = -INFINITY; d[h] = 0.f; acc[h] = 0.f; }

        // 1-deep software pipeline on the k/v gather
        int src = g_col[s];
        float kx[NHEAD], vx[NHEAD];
        {
            const float* kr = g_k + (size_t)src * DIM;
            const float* vr = g_v + (size_t)src * DIM;
            #pragma unroll
            for (int h = 0; h < NHEAD; h++) kx[h] = kr[h * HDIM + lane];
            #pragma unroll
            for (int h = 0; h < NHEAD; h++) vx[h] = vr[h * HDIM + lane];
        }
        for (int i = s; i < e1; i++) {
            float kc[NHEAD], vc[NHEAD];
            #pragma unroll
            for (int h = 0; h < NHEAD; h++) { kc[h] = kx[h]; vc[h] = vx[h]; }
            if (i + 1 < e1) {
                int ns = g_col[i + 1];
                const float* kr = g_k + (size_t)ns * DIM;
                const float* vr = g_v + (size_t)ns * DIM;
                #pragma unroll
                for (int h = 0; h < NHEAD; h++) kx[h] = kr[h * HDIM + lane];
                #pragma unroll
                for (int h = 0; h < NHEAD; h++) vx[h] = vr[h * HDIM + lane];
            }
            #pragma unroll
            for (int h = 0; h < NHEAD; h++) {
                float sc = warp_sum(qv[h] * kc[h]) * SCALE;
                float mn = fmaxf(m[h], sc);
                float c = __expf(m[h] - mn);     // 0 when m was -inf
                float w = __expf(sc - mn);
                d[h] = d[h] * c + w;
                acc[h] = acc[h] * c + w * vc[h];
                m[h] = mn;
            }
        }
        #pragma unroll
        for (int h = 0; h < NHEAD; h++) val[h] += acc[h] / d[h];
    }

    // fused LayerNorm + ReLU (warp holds the full 128-dim row)
    float sum = val[0] + val[1] + val[2] + val[3];
    float sq = val[0] * val[0] + val[1] * val[1] + val[2] * val[2] + val[3] * val[3];
    sum = warp_sum(sum);
    sq = warp_sum(sq);
    float mean = sum * (1.0f / 128.0f);
    float var = sq * (1.0f / 128.0f) - mean * mean;
    float rstd = rsqrtf(var + 1e-5f);
    #pragma unroll
    for (int h = 0; h < NHEAD; h++) {
        float w = lnw[h * HDIM + lane];
        float b = lnb[h * HDIM + lane];
        hr[h * HDIM + lane] = fmaxf((val[h] - mean) * rstd * w + b, 0.0f);
    }
}

// ---------------- K3: segmented pool + high-node gating (one warp per high node) ----------------
__device__ __forceinline__ int lower_bound_batch(const int* __restrict__ batch, int key)
{
    int lo = 0, hi = NLO;
    while (lo < hi) {
        int mid = (lo + hi) >> 1;
        if (batch[mid] < key) lo = mid + 1; else hi = mid;
    }
    return lo;
}

__global__ void __launch_bounds__(256)
pool_final_high(const int* __restrict__ batch, const float* __restrict__ wlh,
                float* __restrict__ out)
{
    int g = blockIdx.x * 8 + threadIdx.y;
    int lane = threadIdx.x;
    int lb = lower_bound_batch(batch, g);
    int ub = lower_bound_batch(batch, g + 1);

    float s[NHEAD] = {0.f, 0.f, 0.f, 0.f};
    for (int j = lb; j < ub; j++) {
        const float* lr = g_h + (size_t)(NHI + j) * DIM;
        #pragma unroll
        for (int h = 0; h < NHEAD; h++) s[h] += lr[h * HDIM + lane];
    }
    float inv = 1.0f / fmaxf((float)(ub - lb), 1.0f);
    float pv[NHEAD];
    #pragma unroll
    for (int h = 0; h < NHEAD; h++) pv[h] = s[h] * inv;

    const float* hrow = g_h + (size_t)g * DIM;
    float hv[NHEAD];
    #pragma unroll
    for (int h = 0; h < NHEAD; h++) hv[h] = hrow[h * HDIM + lane];

    float dot = 0.f;
    #pragma unroll
    for (int h = 0; h < NHEAD; h++)
        dot += hv[h] * wlh[h * HDIM + lane] + pv[h] * wlh[DIM + h * HDIM + lane];
    dot = warp_sum(dot);
    float sgm = 1.0f / (1.0f + __expf(-dot));
    float* O = out + (size_t)g * DIM;
    #pragma unroll
    for (int h = 0; h < NHEAD; h++)
        O[h * HDIM + lane] = sgm * hv[h] + (1.0f - sgm) * pv[h];
}

// ---------------- K4: low-node gating epilogue ----------------
__global__ void final_low(const float* __restrict__ whl, const int* __restrict__ batch,
                          float* __restrict__ out)
{
    int j = blockIdx.x * 8 + threadIdx.y;
    int lane = threadIdx.x;
    int g = batch[j];
    float4 hb = ((const float4*)(g_h + (size_t)g * DIM))[lane];
    float4 lv = ((const float4*)(g_h + (size_t)(NHI + j) * DIM))[lane];
    float4 w0 = ((const float4*)whl)[lane];
    float4 w1 = ((const float4*)(whl + DIM))[lane];
    float d = hb.x * w0.x + hb.y * w0.y + hb.z * w0.z + hb.w * w0.w
            + lv.x * w1.x + lv.y * w1.y + lv.z * w1.z + lv.w * w1.w;
    d = warp_sum(d);
    float a = 1.0f / (1.0f + __expf(-d));
    float4 o;
    o.x = a * lv.x + (1.0f - a) * hb.x;
    o.y = a * lv.y + (1.0f - a) * hb.y;
    o.z = a * lv.z + (1.0f - a) * hb.z;
    o.w = a * lv.w + (1.0f - a) * hb.w;
    ((float4*)(out + (size_t)j * DIM))[lane] = o;
}

// ---------------- launch ----------------
extern "C" void kernel_launch(void* const* d_in, const int* in_sizes, int n_in,
                              void* d_out, int out_size)
{
    const float* high_emb = (const float*)d_in[0];
    const float* low_emb  = (const float*)d_in[1];
    const float* Wq = (const float*)d_in[2];  const float* bq = (const float*)d_in[3];
    const float* Wk = (const float*)d_in[4];  const float* bk = (const float*)d_in[5];
    const float* Wv = (const float*)d_in[6];  const float* bv = (const float*)d_in[7];
    const float* Ws = (const float*)d_in[8];  const float* bs = (const float*)d_in[9];
    const float* lnw = (const float*)d_in[10];
    const float* lnb = (const float*)d_in[11];
    const float* wlh = (const float*)d_in[12];
    const float* whl = (const float*)d_in[13];
    const int* eih   = (const int*)d_in[14];
    const int* eil   = (const int*)d_in[15];
    const int* batch = (const int*)d_in[16];
    float* out = (float*)d_out;

    void* pcnt;
    cudaGetSymbolAddress(&pcnt, g_dcnt);
    cudaMemsetAsync(pcnt, 0, NT * sizeof(int), 0);

    cudaFuncSetAttribute(gemm_hmma, cudaFuncAttributeMaxDynamicSharedMemorySize, SM_BYTES);

    // launch order arranged so gemm_hmma is launch index 4 (ncu -s 5 captures it)
    prep_w<<<256, 256>>>(Wq, Wk, Wv, Ws);                       // 1
    prep_b<<<32, 256>>>(bq, bk, bv, bs);                        // 2
    edge_hist<<<(ET + 255) / 256, 256>>>(eih, eil);             // 3
    gemm_hmma<<<NT / 128, 256, SM_BYTES>>>(high_emb, low_emb);  // 4  <- profiled

    scan_local<<<NBLK, 1024>>>();
    scan_bsum<<<1, 512>>>();
    scan_add<<<NBLK, 1024>>>();
    edge_scatter<<<(ET + 255) / 256, 256>>>(eih, eil);

    dim3 t32x8(32, 8);
    attn_ln<<<NT / 8, t32x8>>>(lnw, lnb);
    pool_final_high<<<NHI / 8, t32x8>>>(batch, wlh, out);
    final_low<<<NLO / 8, t32x8>>>(whl, batch, out + (size_t)NHI * DIM);
}

// round 7
// speedup vs baseline: 1.7088x; 1.0089x over previous
#include <cuda_runtime.h>
#include <cuda_bf16.h>
#include <mma.h>
#include <math.h>
#include <cstdint>

using namespace nvcuda;

#define NHI 4096
#define NLO 262144
#define NT  (NHI + NLO)      /* 266240 = 260 * 1024 */
#define EHI 65536
#define ELO 524288
#define ET  (EHI + ELO)
#define DIM 128
#define NHEAD 4
#define HDIM 32
#define SCALE 0.17677669529663687f   /* 1/sqrt(32) */
#define NBLK 260             /* scan blocks */

// ---------------- scratch (device globals; no allocation allowed) ----------------
__device__ float g_q[(size_t)NT * DIM];
__device__ float g_k[(size_t)NT * DIM];
__device__ float g_v[(size_t)NT * DIM];
__device__ float g_h[(size_t)NT * DIM];      // skip -> +agg+LN+relu in place
__device__ int g_dcnt[NT];
__device__ int g_rowptr[NT + 1];
__device__ int g_cursor[NT];
__device__ int g_col[ET];
__device__ int g_bsum[NBLK];
__device__ int g_bex[NBLK];
// W^T bf16 hi/lo images: [matrix 0..3][n 0..127][k 0..127]
__device__ __align__(16) __nv_bfloat16 g_wt_hi[4 * 128 * 128];
__device__ __align__(16) __nv_bfloat16 g_wt_lo[4 * 128 * 128];
// bias broadcast tiles: [matrix][16 rows][128 cols] (all rows identical)
__device__ __align__(16) float g_btile[4 * 16 * 128];

// ---------------- helpers ----------------
__device__ __forceinline__ float warp_sum(float v) {
    #pragma unroll
    for (int o = 16; o; o >>= 1) v += __shfl_xor_sync(0xffffffffu, v, o);
    return v;
}
__device__ __forceinline__ uint32_t smem_u32(const void* p) {
    uint32_t a;
    asm("{ .reg .u64 t; cvta.to.shared.u64 t, %1; cvt.u32.u64 %0, t; }"
        : "=r"(a) : "l"(p));
    return a;
}
__device__ __forceinline__ void cp_async16(uint32_t dst, const void* src) {
    asm volatile("cp.async.cg.shared.global [%0], [%1], 16;" :: "r"(dst), "l"(src));
}

// ---------------- K0a: prep weights -> W^T bf16 hi/lo ----------------
__global__ void prep_w(const float* __restrict__ Wq, const float* __restrict__ Wk,
                       const float* __restrict__ Wv, const float* __restrict__ Ws)
{
    int idx = blockIdx.x * 256 + threadIdx.x;  // 0..65535
    int m = idx >> 14;       // matrix 0..3
    int n = (idx >> 7) & 127;
    int k = idx & 127;
    const float* W = (m == 0) ? Wq : (m == 1) ? Wk : (m == 2) ? Wv : Ws;
    float w = W[k * 128 + n];
    __nv_bfloat16 hi = __float2bfloat16(w);
    __nv_bfloat16 lo = __float2bfloat16(w - __bfloat162float(hi));
    g_wt_hi[idx] = hi;
    g_wt_lo[idx] = lo;
}

// ---------------- K0b: prep bias tiles ----------------
__global__ void prep_b(const float* __restrict__ bq, const float* __restrict__ bk,
                       const float* __restrict__ bv, const float* __restrict__ bs)
{
    int idx = blockIdx.x * 256 + threadIdx.x;  // 0..8191
    int m = idx >> 11;
    int n = idx & 127;
    const float* B = (m == 0) ? bq : (m == 1) ? bk : (m == 2) ? bv : bs;
    g_btile[idx] = B[n];
}

// ---------------- K1: fused QKV+skip GEMM via HMMA (bf16x3, cp.async, 16 warps) ----------------
// SMEM (bf16 elements): A_hi[128*136], A_lo[128*136], Bbuf0{hi,lo}[2*128*136], Bbuf1{hi,lo}
#define LDA 136
#define A_ELEMS (128 * LDA)            /* 17408 */
#define SM_ALO  A_ELEMS
#define SM_B0   (2 * A_ELEMS)          /* 34816 */
#define SM_B1   (SM_B0 + 2 * A_ELEMS)  /* 69632 */
#define SM_BYTES (2 * (SM_B1 + 2 * A_ELEMS))  /* 104448 elems * 2B = 208896 */

__global__ void __launch_bounds__(512, 1)
gemm_hmma(const float* __restrict__ xh, const float* __restrict__ xl)
{
    extern __shared__ __nv_bfloat16 sm[];
    const uint32_t sbase = smem_u32(sm);
    const int t = threadIdx.x;
    const int wid = t >> 5;
    const int wm = wid & 3;        // warp row group: 32 rows each
    const int wn = wid >> 2;       // warp col group: 32 cols each

    // issue B prefetch for m=0 into buf0 (before A conversion, to overlap)
    {
        const uint4* ghi = (const uint4*)(g_wt_hi);
        const uint4* glo = (const uint4*)(g_wt_lo);
        uint32_t bhi = sbase + SM_B0 * 2;
        uint32_t blo = sbase + (SM_B0 + A_ELEMS) * 2;
        #pragma unroll
        for (int j = 0; j < 4; j++) {
            int idx = t + 512 * j;      // 0..2047 (16B chunks)
            int n = idx >> 4;
            int c = idx & 15;
            uint32_t off = (uint32_t)(n * LDA + c * 8) * 2;
            cp_async16(bhi + off, ghi + idx);
            cp_async16(blo + off, glo + idx);
        }
        asm volatile("cp.async.commit_group;");
    }

    // ---- load + split-convert A tile (128 rows x 128 k) ----
    const int row0 = blockIdx.x * 128;
    const float* X = (row0 < NHI) ? (xh + (size_t)row0 * DIM)
                                  : (xl + (size_t)(row0 - NHI) * DIM);
    #pragma unroll
    for (int j = 0; j < 8; j++) {
        int v = t + 512 * j;            // float4 index 0..4095
        int r = v >> 5;                 // row 0..127
        int k0 = (v & 31) * 4;          // k 0..124
        float4 x = ((const float4*)X)[v];
        float xs[4] = {x.x, x.y, x.z, x.w};
        unsigned short h[4], l[4];
        #pragma unroll
        for (int i = 0; i < 4; i++) {
            __nv_bfloat16 bh = __float2bfloat16(xs[i]);
            __nv_bfloat16 bl = __float2bfloat16(xs[i] - __bfloat162float(bh));
            h[i] = *(unsigned short*)&bh;
            l[i] = *(unsigned short*)&bl;
        }
        uint2 hv = make_uint2((uint32_t)h[0] | ((uint32_t)h[1] << 16),
                              (uint32_t)h[2] | ((uint32_t)h[3] << 16));
        uint2 lv = make_uint2((uint32_t)l[0] | ((uint32_t)l[1] << 16),
                              (uint32_t)l[2] | ((uint32_t)l[3] << 16));
        *(uint2*)(sm + r * LDA + k0)          = hv;
        *(uint2*)(sm + SM_ALO + r * LDA + k0) = lv;
    }

    float* Om[4] = {g_q, g_k, g_v, g_h};

    #pragma unroll
    for (int m = 0; m < 4; m++) {
        // issue prefetch for m+1 into the other buffer
        if (m < 3) {
            const uint4* ghi = (const uint4*)(g_wt_hi + (m + 1) * 128 * 128);
            const uint4* glo = (const uint4*)(g_wt_lo + (m + 1) * 128 * 128);
            int bsel = (m + 1) & 1;
            uint32_t bhi = sbase + (bsel ? SM_B1 : SM_B0) * 2;
            uint32_t blo = bhi + A_ELEMS * 2;
            #pragma unroll
            for (int j = 0; j < 4; j++) {
                int idx = t + 512 * j;
                int n = idx >> 4;
                int c = idx & 15;
                uint32_t off = (uint32_t)(n * LDA + c * 8) * 2;
                cp_async16(bhi + off, ghi + idx);
                cp_async16(blo + off, glo + idx);
            }
            asm volatile("cp.async.commit_group;");
            asm volatile("cp.async.wait_group 1;");
        } else {
            asm volatile("cp.async.wait_group 0;");
        }
        __syncthreads();   // B[m] ready; prior phase readers done

        const __nv_bfloat16* Bhi = sm + ((m & 1) ? SM_B1 : SM_B0);
        const __nv_bfloat16* Blo = Bhi + A_ELEMS;

        wmma::fragment<wmma::accumulator, 16, 16, 16, float> acc[2][2];
        #pragma unroll
        for (int i = 0; i < 2; i++)
            #pragma unroll
            for (int j = 0; j < 2; j++)
                wmma::load_matrix_sync(acc[i][j],
                    g_btile + m * 16 * 128 + wn * 32 + j * 16, 128,
                    wmma::mem_row_major);

        #pragma unroll
        for (int ks = 0; ks < 8; ks++) {
            wmma::fragment<wmma::matrix_a, 16, 16, 16, __nv_bfloat16, wmma::row_major> ah[2], al[2];
            wmma::fragment<wmma::matrix_b, 16, 16, 16, __nv_bfloat16, wmma::col_major> bh[2], bl[2];
            #pragma unroll
            for (int i = 0; i < 2; i++) {
                int r = wm * 32 + i * 16;
                wmma::load_matrix_sync(ah[i], sm + r * LDA + ks * 16, LDA);
                wmma::load_matrix_sync(al[i], sm + SM_ALO + r * LDA + ks * 16, LDA);
            }
            #pragma unroll
            for (int j = 0; j < 2; j++) {
                int n = wn * 32 + j * 16;
                wmma::load_matrix_sync(bh[j], Bhi + n * LDA + ks * 16, LDA);
                wmma::load_matrix_sync(bl[j], Blo + n * LDA + ks * 16, LDA);
            }
            #pragma unroll
            for (int i = 0; i < 2; i++)
                #pragma unroll
                for (int j = 0; j < 2; j++) {
                    wmma::mma_sync(acc[i][j], ah[i], bh[j], acc[i][j]);
                    wmma::mma_sync(acc[i][j], al[i], bh[j], acc[i][j]);
                    wmma::mma_sync(acc[i][j], ah[i], bl[j], acc[i][j]);
                }
        }

        float* O = Om[m] + (size_t)row0 * DIM;
        #pragma unroll
        for (int i = 0; i < 2; i++)
            #pragma unroll
            for (int j = 0; j < 2; j++)
                wmma::store_matrix_sync(
                    O + (size_t)(wm * 32 + i * 16) * DIM + wn * 32 + j * 16,
                    acc[i][j], DIM, wmma::mem_row_major);
        __syncthreads();   // all warps done reading B[m] before its buffer is refilled
    }
}

// ---------------- CSR build ----------------
__global__ void edge_hist(const int* __restrict__ eih, const int* __restrict__ eil)
{
    int e = blockIdx.x * 256 + threadIdx.x;
    if (e >= ET) return;
    int dst = (e < EHI) ? eih[EHI + e] : (eil[ELO + (e - EHI)] + NHI);
    atomicAdd(&g_dcnt[dst], 1);
}

__global__ void scan_local()
{
    __shared__ int sh[1024];
    const int t = threadIdx.x;
    const int i = blockIdx.x * 1024 + t;
    int v = g_dcnt[i];
    sh[t] = v;
    __syncthreads();
    #pragma unroll
    for (int off = 1; off < 1024; off <<= 1) {
        int u = (t >= off) ? sh[t - off] : 0;
        __syncthreads();
        sh[t] += u;
        __syncthreads();
    }
    g_rowptr[i] = sh[t] - v;            // local exclusive
    if (t == 1023) g_bsum[blockIdx.x] = sh[t];
}

__global__ void scan_bsum()
{
    __shared__ int sh[512];
    const int t = threadIdx.x;          // 512 threads
    int v = (t < NBLK) ? g_bsum[t] : 0;
    sh[t] = v;
    __syncthreads();
    #pragma unroll
    for (int off = 1; off < 512; off <<= 1) {
        int u = (t >= off) ? sh[t - off] : 0;
        __syncthreads();
        sh[t] += u;
        __syncthreads();
    }
    if (t < NBLK) g_bex[t] = sh[t] - v; // exclusive block base
    if (t == 511) g_rowptr[NT] = sh[511];
}

__global__ void scan_add()
{
    const int i = blockIdx.x * 1024 + threadIdx.x;
    int r = g_rowptr[i] + g_bex[blockIdx.x];
    g_rowptr[i] = r;
    g_cursor[i] = r;
}

__global__ void edge_scatter(const int* __restrict__ eih, const int* __restrict__ eil)
{
    int e = blockIdx.x * 256 + threadIdx.x;
    if (e >= ET) return;
    int src, dst;
    if (e < EHI) { src = eih[e];             dst = eih[EHI + e]; }
    else         { src = eil[e - EHI] + NHI; dst = eil[ELO + (e - EHI)] + NHI; }
    int pos = atomicAdd(&g_cursor[dst], 1);
    g_col[pos] = src;
}

// ---------------- K2: one-pass attention (online softmax) + fused LN/ReLU ----------------
__global__ void __launch_bounds__(256)
attn_ln(const float* __restrict__ lnw, const float* __restrict__ lnb)
{
    int node = blockIdx.x * 8 + threadIdx.y;
    int lane = threadIdx.x;
    int s = g_rowptr[node];
    int e1 = g_rowptr[node + 1];

    float val[NHEAD];
    float* hr = g_h + (size_t)node * DIM;
    #pragma unroll
    for (int h = 0; h < NHEAD; h++) val[h] = hr[h * HDIM + lane];  // skip term

    if (s < e1) {
        const float* qr = g_q + (size_t)node * DIM;
        float qv[NHEAD];
        #pragma unroll
        for (int h = 0; h < NHEAD; h++) qv[h] = qr[h * HDIM + lane];

        float m[NHEAD], d[NHEAD], acc[NHEAD];
        #pragma unroll
        for (int h = 0; h < NHEAD; h++) { m[h] = -INFINITY; d[h] = 0.f; acc[h] = 0.f; }

        // 1-deep software pipeline on the k/v gather
        int src = g_col[s];
        float kx[NHEAD], vx[NHEAD];
        {
            const float* kr = g_k + (size_t)src * DIM;
            const float* vr = g_v + (size_t)src * DIM;
            #pragma unroll
            for (int h = 0; h < NHEAD; h++) kx[h] = kr[h * HDIM + lane];
            #pragma unroll
            for (int h = 0; h < NHEAD; h++) vx[h] = vr[h * HDIM + lane];
        }
        for (int i = s; i < e1; i++) {
            float kc[NHEAD], vc[NHEAD];
            #pragma unroll
            for (int h = 0; h < NHEAD; h++) { kc[h] = kx[h]; vc[h] = vx[h]; }
            if (i + 1 < e1) {
                int ns = g_col[i + 1];
                const float* kr = g_k + (size_t)ns * DIM;
                const float* vr = g_v + (size_t)ns * DIM;
                #pragma unroll
                for (int h = 0; h < NHEAD; h++) kx[h] = kr[h * HDIM + lane];
                #pragma unroll
                for (int h = 0; h < NHEAD; h++) vx[h] = vr[h * HDIM + lane];
            }
            #pragma unroll
            for (int h = 0; h < NHEAD; h++) {
                float sc = warp_sum(qv[h] * kc[h]) * SCALE;
                float mn = fmaxf(m[h], sc);
                float c = __expf(m[h] - mn);     // 0 when m was -inf
                float w = __expf(sc - mn);
                d[h] = d[h] * c + w;
                acc[h] = acc[h] * c + w * vc[h];
                m[h] = mn;
            }
        }
        #pragma unroll
        for (int h = 0; h < NHEAD; h++) val[h] += acc[h] / d[h];
    }

    // fused LayerNorm + ReLU (warp holds the full 128-dim row)
    float sum = val[0] + val[1] + val[2] + val[3];
    float sq = val[0] * val[0] + val[1] * val[1] + val[2] * val[2] + val[3] * val[3];
    sum = warp_sum(sum);
    sq = warp_sum(sq);
    float mean = sum * (1.0f / 128.0f);
    float var = sq * (1.0f / 128.0f) - mean * mean;
    float rstd = rsqrtf(var + 1e-5f);
    #pragma unroll
    for (int h = 0; h < NHEAD; h++) {
        float w = lnw[h * HDIM + lane];
        float b = lnb[h * HDIM + lane];
        hr[h * HDIM + lane] = fmaxf((val[h] - mean) * rstd * w + b, 0.0f);
    }
}

// ---------------- K3: segmented pool + high-node gating (one warp per high node) ----------------
__device__ __forceinline__ int lower_bound_batch(const int* __restrict__ batch, int key)
{
    int lo = 0, hi = NLO;
    while (lo < hi) {
        int mid = (lo + hi) >> 1;
        if (batch[mid] < key) lo = mid + 1; else hi = mid;
    }
    return lo;
}

__global__ void __launch_bounds__(256)
pool_final_high(const int* __restrict__ batch, const float* __restrict__ wlh,
                float* __restrict__ out)
{
    int g = blockIdx.x * 8 + threadIdx.y;
    int lane = threadIdx.x;
    int lb = lower_bound_batch(batch, g);
    int ub = lower_bound_batch(batch, g + 1);

    float s[NHEAD] = {0.f, 0.f, 0.f, 0.f};
    for (int j = lb; j < ub; j++) {
        const float* lr = g_h + (size_t)(NHI + j) * DIM;
        #pragma unroll
        for (int h = 0; h < NHEAD; h++) s[h] += lr[h * HDIM + lane];
    }
    float inv = 1.0f / fmaxf((float)(ub - lb), 1.0f);
    float pv[NHEAD];
    #pragma unroll
    for (int h = 0; h < NHEAD; h++) pv[h] = s[h] * inv;

    const float* hrow = g_h + (size_t)g * DIM;
    float hv[NHEAD];
    #pragma unroll
    for (int h = 0; h < NHEAD; h++) hv[h] = hrow[h * HDIM + lane];

    float dot = 0.f;
    #pragma unroll
    for (int h = 0; h < NHEAD; h++)
        dot += hv[h] * wlh[h * HDIM + lane] + pv[h] * wlh[DIM + h * HDIM + lane];
    dot = warp_sum(dot);
    float sgm = 1.0f / (1.0f + __expf(-dot));
    float* O = out + (size_t)g * DIM;
    #pragma unroll
    for (int h = 0; h < NHEAD; h++)
        O[h * HDIM + lane] = sgm * hv[h] + (1.0f - sgm) * pv[h];
}

// ---------------- K4: low-node gating epilogue ----------------
__global__ void final_low(const float* __restrict__ whl, const int* __restrict__ batch,
                          float* __restrict__ out)
{
    int j = blockIdx.x * 8 + threadIdx.y;
    int lane = threadIdx.x;
    int g = batch[j];
    float4 hb = ((const float4*)(g_h + (size_t)g * DIM))[lane];
    float4 lv = ((const float4*)(g_h + (size_t)(NHI + j) * DIM))[lane];
    float4 w0 = ((const float4*)whl)[lane];
    float4 w1 = ((const float4*)(whl + DIM))[lane];
    float d = hb.x * w0.x + hb.y * w0.y + hb.z * w0.z + hb.w * w0.w
            + lv.x * w1.x + lv.y * w1.y + lv.z * w1.z + lv.w * w1.w;
    d = warp_sum(d);
    float a = 1.0f / (1.0f + __expf(-d));
    float4 o;
    o.x = a * lv.x + (1.0f - a) * hb.x;
    o.y = a * lv.y + (1.0f - a) * hb.y;
    o.z = a * lv.z + (1.0f - a) * hb.z;
    o.w = a * lv.w + (1.0f - a) * hb.w;
    ((float4*)(out + (size_t)j * DIM))[lane] = o;
}

// ---------------- launch ----------------
extern "C" void kernel_launch(void* const* d_in, const int* in_sizes, int n_in,
                              void* d_out, int out_size)
{
    const float* high_emb = (const float*)d_in[0];
    const float* low_emb  = (const float*)d_in[1];
    const float* Wq = (const float*)d_in[2];  const float* bq = (const float*)d_in[3];
    const float* Wk = (const float*)d_in[4];  const float* bk = (const float*)d_in[5];
    const float* Wv = (const float*)d_in[6];  const float* bv = (const float*)d_in[7];
    const float* Ws = (const float*)d_in[8];  const float* bs = (const float*)d_in[9];
    const float* lnw = (const float*)d_in[10];
    const float* lnb = (const float*)d_in[11];
    const float* wlh = (const float*)d_in[12];
    const float* whl = (const float*)d_in[13];
    const int* eih   = (const int*)d_in[14];
    const int* eil   = (const int*)d_in[15];
    const int* batch = (const int*)d_in[16];
    float* out = (float*)d_out;

    void* pcnt;
    cudaGetSymbolAddress(&pcnt, g_dcnt);
    cudaMemsetAsync(pcnt, 0, NT * sizeof(int), 0);

    cudaFuncSetAttribute(gemm_hmma, cudaFuncAttributeMaxDynamicSharedMemorySize, SM_BYTES);

    // launch order arranged so gemm_hmma is launch index 4 (ncu -s 5 captures it)
    prep_w<<<256, 256>>>(Wq, Wk, Wv, Ws);                       // 1
    prep_b<<<32, 256>>>(bq, bk, bv, bs);                        // 2
    edge_hist<<<(ET + 255) / 256, 256>>>(eih, eil);             // 3
    gemm_hmma<<<NT / 128, 512, SM_BYTES>>>(high_emb, low_emb);  // 4  <- profiled

    scan_local<<<NBLK, 1024>>>();
    scan_bsum<<<1, 512>>>();
    scan_add<<<NBLK, 1024>>>();
    edge_scatter<<<(ET + 255) / 256, 256>>>(eih, eil);

    dim3 t32x8(32, 8);
    attn_ln<<<NT / 8, t32x8>>>(lnw, lnb);
    pool_final_high<<<NHI / 8, t32x8>>>(batch, wlh, out);
    final_low<<<NLO / 8, t32x8>>>(whl, batch, out + (size_t)NHI * DIM);
}

// round 8
// speedup vs baseline: 1.8023x; 1.0547x over previous
#include <cuda_runtime.h>
#include <cuda_bf16.h>
#include <mma.h>
#include <math.h>
#include <cstdint>

using namespace nvcuda;

#define NHI 4096
#define NLO 262144
#define NT  (NHI + NLO)      /* 266240 = 260 * 1024 */
#define EHI 65536
#define ELO 524288
#define ET  (EHI + ELO)
#define DIM 128
#define NHEAD 4
#define HDIM 32
#define SCALE 0.17677669529663687f   /* 1/sqrt(32) */
#define NBLK 260             /* scan blocks */

// ---------------- scratch (device globals; no allocation allowed) ----------------
__device__ float g_q[(size_t)NT * DIM];
__device__ float g_kv[(size_t)NT * 256];     // k at +0, v at +128 (interleaved rows)
__device__ float g_h[(size_t)NT * DIM];      // skip -> +agg+LN+relu in place
__device__ int g_dcnt[NT];
__device__ int g_rowptr[NT + 1];
__device__ int g_cursor[NT];
__device__ int g_col[ET];
__device__ int g_bsum[NBLK];
__device__ int g_bex[NBLK];
// W^T bf16 hi/lo images: [matrix 0..3][n 0..127][k 0..127]
__device__ __align__(16) __nv_bfloat16 g_wt_hi[4 * 128 * 128];
__device__ __align__(16) __nv_bfloat16 g_wt_lo[4 * 128 * 128];
// bias rows: [matrix][128]
__device__ __align__(16) float g_brow[4 * 128];

// ---------------- helpers ----------------
__device__ __forceinline__ float warp_sum(float v) {
    #pragma unroll
    for (int o = 16; o; o >>= 1) v += __shfl_xor_sync(0xffffffffu, v, o);
    return v;
}
__device__ __forceinline__ uint32_t smem_u32(const void* p) {
    uint32_t a;
    asm("{ .reg .u64 t; cvta.to.shared.u64 t, %1; cvt.u32.u64 %0, t; }"
        : "=r"(a) : "l"(p));
    return a;
}
__device__ __forceinline__ void cp_async16(uint32_t dst, const void* src) {
    asm volatile("cp.async.cg.shared.global [%0], [%1], 16;" :: "r"(dst), "l"(src));
}

// ---------------- K0a: prep weights -> W^T bf16 hi/lo ----------------
__global__ void prep_w(const float* __restrict__ Wq, const float* __restrict__ Wk,
                       const float* __restrict__ Wv, const float* __restrict__ Ws)
{
    int idx = blockIdx.x * 256 + threadIdx.x;  // 0..65535
    int m = idx >> 14;       // matrix 0..3
    int n = (idx >> 7) & 127;
    int k = idx & 127;
    const float* W = (m == 0) ? Wq : (m == 1) ? Wk : (m == 2) ? Wv : Ws;
    float w = W[k * 128 + n];
    __nv_bfloat16 hi = __float2bfloat16(w);
    __nv_bfloat16 lo = __float2bfloat16(w - __bfloat162float(hi));
    g_wt_hi[idx] = hi;
    g_wt_lo[idx] = lo;
}

// ---------------- K0b: prep bias rows ----------------
__global__ void prep_b(const float* __restrict__ bq, const float* __restrict__ bk,
                       const float* __restrict__ bv, const float* __restrict__ bs)
{
    int idx = blockIdx.x * 256 + threadIdx.x;  // 0..511
    int m = idx >> 7;
    int n = idx & 127;
    const float* B = (m == 0) ? bq : (m == 1) ? bk : (m == 2) ? bv : bs;
    g_brow[idx] = B[n];
}

// ---------------- K1: fused QKV+skip GEMM via HMMA (bf16x3, cp.async, 16 warps) ----------------
// SMEM (bf16 elems): A_hi, A_lo, Bbuf0{hi,lo}, Bbuf1{hi,lo}, then 8KB fp32 bias tile
#define LDA 136
#define A_ELEMS (128 * LDA)            /* 17408 */
#define SM_ALO  A_ELEMS
#define SM_B0   (2 * A_ELEMS)          /* 34816 */
#define SM_B1   (SM_B0 + 2 * A_ELEMS)  /* 69632 */
#define SM_BIAS_ELEMS (SM_B1 + 2 * A_ELEMS)   /* 104448 bf16 elems */
#define SM_BYTES (SM_BIAS_ELEMS * 2 + 16 * 128 * 4)  /* 208896 + 8192 = 217088 */

__global__ void __launch_bounds__(512, 1)
gemm_hmma(const float* __restrict__ xh, const float* __restrict__ xl)
{
    extern __shared__ __nv_bfloat16 sm[];
    float* bias_s = (float*)(sm + SM_BIAS_ELEMS);   // 16 x 128 fp32
    const uint32_t sbase = smem_u32(sm);
    const int t = threadIdx.x;
    const int wid = t >> 5;
    const int wm = wid & 3;        // warp row group: 32 rows each
    const int wn = wid >> 2;       // warp col group: 32 cols each

    // issue B prefetch for m=0 into buf0 (before A conversion, to overlap)
    {
        const uint4* ghi = (const uint4*)(g_wt_hi);
        const uint4* glo = (const uint4*)(g_wt_lo);
        uint32_t bhi = sbase + SM_B0 * 2;
        uint32_t blo = sbase + (SM_B0 + A_ELEMS) * 2;
        #pragma unroll
        for (int j = 0; j < 4; j++) {
            int idx = t + 512 * j;      // 0..2047 (16B chunks)
            int n = idx >> 4;
            int c = idx & 15;
            uint32_t off = (uint32_t)(n * LDA + c * 8) * 2;
            cp_async16(bhi + off, ghi + idx);
            cp_async16(blo + off, glo + idx);
        }
        asm volatile("cp.async.commit_group;");
    }

    // ---- load + split-convert A tile (128 rows x 128 k) ----
    const int row0 = blockIdx.x * 128;
    const float* X = (row0 < NHI) ? (xh + (size_t)row0 * DIM)
                                  : (xl + (size_t)(row0 - NHI) * DIM);
    #pragma unroll
    for (int j = 0; j < 8; j++) {
        int v = t + 512 * j;            // float4 index 0..4095
        int r = v >> 5;                 // row 0..127
        int k0 = (v & 31) * 4;          // k 0..124
        float4 x = ((const float4*)X)[v];
        float xs[4] = {x.x, x.y, x.z, x.w};
        unsigned short h[4], l[4];
        #pragma unroll
        for (int i = 0; i < 4; i++) {
            __nv_bfloat16 bh = __float2bfloat16(xs[i]);
            __nv_bfloat16 bl = __float2bfloat16(xs[i] - __bfloat162float(bh));
            h[i] = *(unsigned short*)&bh;
            l[i] = *(unsigned short*)&bl;
        }
        uint2 hv = make_uint2((uint32_t)h[0] | ((uint32_t)h[1] << 16),
                              (uint32_t)h[2] | ((uint32_t)h[3] << 16));
        uint2 lv = make_uint2((uint32_t)l[0] | ((uint32_t)l[1] << 16),
                              (uint32_t)l[2] | ((uint32_t)l[3] << 16));
        *(uint2*)(sm + r * LDA + k0)          = hv;
        *(uint2*)(sm + SM_ALO + r * LDA + k0) = lv;
    }

    float* Obase[4] = {g_q, g_kv, g_kv + 128, g_h};
    const int ldo[4] = {128, 256, 256, 128};

    #pragma unroll
    for (int m = 0; m < 4; m++) {
        // issue prefetch for m+1 into the other buffer
        if (m < 3) {
            const uint4* ghi = (const uint4*)(g_wt_hi + (m + 1) * 128 * 128);
            const uint4* glo = (const uint4*)(g_wt_lo + (m + 1) * 128 * 128);
            int bsel = (m + 1) & 1;
            uint32_t bhi = sbase + (bsel ? SM_B1 : SM_B0) * 2;
            uint32_t blo = bhi + A_ELEMS * 2;
            #pragma unroll
            for (int j = 0; j < 4; j++) {
                int idx = t + 512 * j;
                int n = idx >> 4;
                int c = idx & 15;
                uint32_t off = (uint32_t)(n * LDA + c * 8) * 2;
                cp_async16(bhi + off, ghi + idx);
                cp_async16(blo + off, glo + idx);
            }
            asm volatile("cp.async.commit_group;");
            asm volatile("cp.async.wait_group 1;");
        } else {
            asm volatile("cp.async.wait_group 0;");
        }
        // stage bias rows (16 identical rows) into smem for acc init
        {
            float b = g_brow[m * 128 + (t & 127)];
            #pragma unroll
            for (int r = t >> 7; r < 16; r += 4)
                bias_s[r * 128 + (t & 127)] = b;
        }
        __syncthreads();   // B[m]+bias ready; prior phase readers done

        const __nv_bfloat16* Bhi = sm + ((m & 1) ? SM_B1 : SM_B0);
        const __nv_bfloat16* Blo = Bhi + A_ELEMS;

        wmma::fragment<wmma::accumulator, 16, 16, 16, float> acc[2][2];
        #pragma unroll
        for (int i = 0; i < 2; i++)
            #pragma unroll
            for (int j = 0; j < 2; j++)
                wmma::load_matrix_sync(acc[i][j],
                    bias_s + wn * 32 + j * 16, 128, wmma::mem_row_major);

        #pragma unroll
        for (int ks = 0; ks < 8; ks++) {
            wmma::fragment<wmma::matrix_a, 16, 16, 16, __nv_bfloat16, wmma::row_major> ah[2], al[2];
            wmma::fragment<wmma::matrix_b, 16, 16, 16, __nv_bfloat16, wmma::col_major> bh[2], bl[2];
            #pragma unroll
            for (int i = 0; i < 2; i++) {
                int r = wm * 32 + i * 16;
                wmma::load_matrix_sync(ah[i], sm + r * LDA + ks * 16, LDA);
                wmma::load_matrix_sync(al[i], sm + SM_ALO + r * LDA + ks * 16, LDA);
            }
            #pragma unroll
            for (int j = 0; j < 2; j++) {
                int n = wn * 32 + j * 16;
                wmma::load_matrix_sync(bh[j], Bhi + n * LDA + ks * 16, LDA);
                wmma::load_matrix_sync(bl[j], Blo + n * LDA + ks * 16, LDA);
            }
            #pragma unroll
            for (int i = 0; i < 2; i++)
                #pragma unroll
                for (int j = 0; j < 2; j++) {
                    wmma::mma_sync(acc[i][j], ah[i], bh[j], acc[i][j]);
                    wmma::mma_sync(acc[i][j], al[i], bh[j], acc[i][j]);
                    wmma::mma_sync(acc[i][j], ah[i], bl[j], acc[i][j]);
                }
        }

        float* O = Obase[m] + (size_t)row0 * ldo[m];
        #pragma unroll
        for (int i = 0; i < 2; i++)
            #pragma unroll
            for (int j = 0; j < 2; j++)
                wmma::store_matrix_sync(
                    O + (size_t)(wm * 32 + i * 16) * ldo[m] + wn * 32 + j * 16,
                    acc[i][j], ldo[m], wmma::mem_row_major);
        __syncthreads();   // all warps done reading B[m]/bias before refill
    }
}

// ---------------- CSR build ----------------
__global__ void edge_hist(const int* __restrict__ eih, const int* __restrict__ eil)
{
    int e = blockIdx.x * 256 + threadIdx.x;
    if (e >= ET) return;
    int dst = (e < EHI) ? eih[EHI + e] : (eil[ELO + (e - EHI)] + NHI);
    atomicAdd(&g_dcnt[dst], 1);
}

__global__ void scan_local()
{
    __shared__ int sh[1024];
    const int t = threadIdx.x;
    const int i = blockIdx.x * 1024 + t;
    int v = g_dcnt[i];
    sh[t] = v;
    __syncthreads();
    #pragma unroll
    for (int off = 1; off < 1024; off <<= 1) {
        int u = (t >= off) ? sh[t - off] : 0;
        __syncthreads();
        sh[t] += u;
        __syncthreads();
    }
    g_rowptr[i] = sh[t] - v;            // local exclusive
    if (t == 1023) g_bsum[blockIdx.x] = sh[t];
}

__global__ void scan_bsum()
{
    __shared__ int sh[512];
    const int t = threadIdx.x;          // 512 threads
    int v = (t < NBLK) ? g_bsum[t] : 0;
    sh[t] = v;
    __syncthreads();
    #pragma unroll
    for (int off = 1; off < 512; off <<= 1) {
        int u = (t >= off) ? sh[t - off] : 0;
        __syncthreads();
        sh[t] += u;
        __syncthreads();
    }
    if (t < NBLK) g_bex[t] = sh[t] - v; // exclusive block base
    if (t == 511) g_rowptr[NT] = sh[511];
}

__global__ void scan_add()
{
    const int i = blockIdx.x * 1024 + threadIdx.x;
    int r = g_rowptr[i] + g_bex[blockIdx.x];
    g_rowptr[i] = r;
    g_cursor[i] = r;
}

__global__ void edge_scatter(const int* __restrict__ eih, const int* __restrict__ eil)
{
    int e = blockIdx.x * 256 + threadIdx.x;
    if (e >= ET) return;
    int src, dst;
    if (e < EHI) { src = eih[e];             dst = eih[EHI + e]; }
    else         { src = eil[e - EHI] + NHI; dst = eil[ELO + (e - EHI)] + NHI; }
    int pos = atomicAdd(&g_cursor[dst], 1);
    g_col[pos] = src;
}

// ---------------- K2: one-pass attention (online softmax) + fused LN/ReLU ----------------
// lane owns 4 contiguous columns [lane*4, lane*4+4); head = lane>>3.
__global__ void __launch_bounds__(256)
attn_ln(const float* __restrict__ lnw, const float* __restrict__ lnb)
{
    int node = blockIdx.x * 8 + threadIdx.y;
    int lane = threadIdx.x;
    int s = g_rowptr[node];
    int e1 = g_rowptr[node + 1];

    float* hr = g_h + (size_t)node * DIM;
    float4 val = ((float4*)hr)[lane];   // skip term

    if (s < e1) {
        float4 qv = ((const float4*)(g_q + (size_t)node * DIM))[lane];

        float m = -INFINITY, d = 0.f;
        float4 acc = make_float4(0.f, 0.f, 0.f, 0.f);

        // 1-deep software pipeline on the kv gather (1KB contiguous per edge)
        const float4* kvp = (const float4*)(g_kv + (size_t)g_col[s] * 256);
        float4 k4 = kvp[lane];
        float4 v4 = kvp[lane + 32];
        for (int i = s; i < e1; i++) {
            float4 kc = k4, vc = v4;
            if (i + 1 < e1) {
                const float4* np = (const float4*)(g_kv + (size_t)g_col[i + 1] * 256);
                k4 = np[lane];
                v4 = np[lane + 32];
            }
            // per-lane partial dot over its 4 cols, butterfly within 8-lane head group
            float p = qv.x * kc.x + qv.y * kc.y + qv.z * kc.z + qv.w * kc.w;
            p += __shfl_xor_sync(0xffffffffu, p, 4);
            p += __shfl_xor_sync(0xffffffffu, p, 2);
            p += __shfl_xor_sync(0xffffffffu, p, 1);
            float sc = p * SCALE;            // this lane's head score
            float mn = fmaxf(m, sc);
            float c = __expf(m - mn);        // 0 when m was -inf
            float w = __expf(sc - mn);
            d = d * c + w;
            acc.x = acc.x * c + w * vc.x;
            acc.y = acc.y * c + w * vc.y;
            acc.z = acc.z * c + w * vc.z;
            acc.w = acc.w * c + w * vc.w;
            m = mn;
        }
        float inv = 1.0f / d;
        val.x += acc.x * inv;
        val.y += acc.y * inv;
        val.z += acc.z * inv;
        val.w += acc.w * inv;
    }

    // fused LayerNorm + ReLU (warp holds the full 128-dim row)
    float sum = warp_sum(val.x + val.y + val.z + val.w);
    float sq = warp_sum(val.x * val.x + val.y * val.y + val.z * val.z + val.w * val.w);
    float mean = sum * (1.0f / 128.0f);
    float var = sq * (1.0f / 128.0f) - mean * mean;
    float rstd = rsqrtf(var + 1e-5f);
    float4 w4 = ((const float4*)lnw)[lane];
    float4 b4 = ((const float4*)lnb)[lane];
    float4 o;
    o.x = fmaxf((val.x - mean) * rstd * w4.x + b4.x, 0.0f);
    o.y = fmaxf((val.y - mean) * rstd * w4.y + b4.y, 0.0f);
    o.z = fmaxf((val.z - mean) * rstd * w4.z + b4.z, 0.0f);
    o.w = fmaxf((val.w - mean) * rstd * w4.w + b4.w, 0.0f);
    ((float4*)hr)[lane] = o;
}

// ---------------- K3: segmented pool + high-node gating (one warp per high node) ----------------
__device__ __forceinline__ int lower_bound_batch(const int* __restrict__ batch, int key)
{
    int lo = 0, hi = NLO;
    while (lo < hi) {
        int mid = (lo + hi) >> 1;
        if (batch[mid] < key) lo = mid + 1; else hi = mid;
    }
    return lo;
}

__global__ void __launch_bounds__(256)
pool_final_high(const int* __restrict__ batch, const float* __restrict__ wlh,
                float* __restrict__ out)
{
    int g = blockIdx.x * 8 + threadIdx.y;
    int lane = threadIdx.x;
    int lb = lower_bound_batch(batch, g);
    int ub = lower_bound_batch(batch, g + 1);

    float4 s = make_float4(0.f, 0.f, 0.f, 0.f);
    for (int j = lb; j < ub; j++) {
        float4 lr = ((const float4*)(g_h + (size_t)(NHI + j) * DIM))[lane];
        s.x += lr.x; s.y += lr.y; s.z += lr.z; s.w += lr.w;
    }
    float inv = 1.0f / fmaxf((float)(ub - lb), 1.0f);
    float4 pv = make_float4(s.x * inv, s.y * inv, s.z * inv, s.w * inv);

    float4 hv = ((const float4*)(g_h + (size_t)g * DIM))[lane];
    float4 w0 = ((const float4*)wlh)[lane];
    float4 w1 = ((const float4*)(wlh + DIM))[lane];
    float dot = hv.x * w0.x + hv.y * w0.y + hv.z * w0.z + hv.w * w0.w
              + pv.x * w1.x + pv.y * w1.y + pv.z * w1.z + pv.w * w1.w;
    dot = warp_sum(dot);
    float sgm = 1.0f / (1.0f + __expf(-dot));
    float4 o;
    o.x = sgm * hv.x + (1.0f - sgm) * pv.x;
    o.y = sgm * hv.y + (1.0f - sgm) * pv.y;
    o.z = sgm * hv.z + (1.0f - sgm) * pv.z;
    o.w = sgm * hv.w + (1.0f - sgm) * pv.w;
    ((float4*)(out + (size_t)g * DIM))[lane] = o;
}

// ---------------- K4: low-node gating epilogue ----------------
__global__ void final_low(const float* __restrict__ whl, const int* __restrict__ batch,
                          float* __restrict__ out)
{
    int j = blockIdx.x * 8 + threadIdx.y;
    int lane = threadIdx.x;
    int g = batch[j];
    float4 hb = ((const float4*)(g_h + (size_t)g * DIM))[lane];
    float4 lv = ((const float4*)(g_h + (size_t)(NHI + j) * DIM))[lane];
    float4 w0 = ((const float4*)whl)[lane];
    float4 w1 = ((const float4*)(whl + DIM))[lane];
    float d = hb.x * w0.x + hb.y * w0.y + hb.z * w0.z + hb.w * w0.w
            + lv.x * w1.x + lv.y * w1.y + lv.z * w1.z + lv.w * w1.w;
    d = warp_sum(d);
    float a = 1.0f / (1.0f + __expf(-d));
    float4 o;
    o.x = a * lv.x + (1.0f - a) * hb.x;
    o.y = a * lv.y + (1.0f - a) * hb.y;
    o.z = a * lv.z + (1.0f - a) * hb.z;
    o.w = a * lv.w + (1.0f - a) * hb.w;
    ((float4*)(out + (size_t)j * DIM))[lane] = o;
}

// ---------------- launch ----------------
extern "C" void kernel_launch(void* const* d_in, const int* in_sizes, int n_in,
                              void* d_out, int out_size)
{
    const float* high_emb = (const float*)d_in[0];
    const float* low_emb  = (const float*)d_in[1];
    const float* Wq = (const float*)d_in[2];  const float* bq = (const float*)d_in[3];
    const float* Wk = (const float*)d_in[4];  const float* bk = (const float*)d_in[5];
    const float* Wv = (const float*)d_in[6];  const float* bv = (const float*)d_in[7];
    const float* Ws = (const float*)d_in[8];  const float* bs = (const float*)d_in[9];
    const float* lnw = (const float*)d_in[10];
    const float* lnb = (const float*)d_in[11];
    const float* wlh = (const float*)d_in[12];
    const float* whl = (const float*)d_in[13];
    const int* eih   = (const int*)d_in[14];
    const int* eil   = (const int*)d_in[15];
    const int* batch = (const int*)d_in[16];
    float* out = (float*)d_out;

    void* pcnt;
    cudaGetSymbolAddress(&pcnt, g_dcnt);
    cudaMemsetAsync(pcnt, 0, NT * sizeof(int), 0);

    cudaFuncSetAttribute(gemm_hmma, cudaFuncAttributeMaxDynamicSharedMemorySize, SM_BYTES);

    // launch order keeps gemm_hmma at the profiled slot
    prep_w<<<256, 256>>>(Wq, Wk, Wv, Ws);                       // 1
    prep_b<<<2, 256>>>(bq, bk, bv, bs);                         // 2
    edge_hist<<<(ET + 255) / 256, 256>>>(eih, eil);             // 3
    gemm_hmma<<<NT / 128, 512, SM_BYTES>>>(high_emb, low_emb);  // 4  <- profiled

    scan_local<<<NBLK, 1024>>>();
    scan_bsum<<<1, 512>>>();
    scan_add<<<NBLK, 1024>>>();
    edge_scatter<<<(ET + 255) / 256, 256>>>(eih, eil);

    dim3 t32x8(32, 8);
    attn_ln<<<NT / 8, t32x8>>>(lnw, lnb);
    pool_final_high<<<NHI / 8, t32x8>>>(batch, wlh, out);
    final_low<<<NLO / 8, t32x8>>>(whl, batch, out + (size_t)NHI * DIM);
}

// round 9
// speedup vs baseline: 1.8752x; 1.0404x over previous
#include <cuda_runtime.h>
#include <cuda_bf16.h>
#include <mma.h>
#include <math.h>
#include <cstdint>

using namespace nvcuda;

#define NHI 4096
#define NLO 262144
#define NT  (NHI + NLO)      /* 266240 = 260 * 1024 */
#define EHI 65536
#define ELO 524288
#define ET  (EHI + ELO)
#define DIM 128
#define NHEAD 4
#define HDIM 32
#define SCALE 0.17677669529663687f   /* 1/sqrt(32) */
#define NBLK 260             /* scan blocks */

// ---------------- scratch (device globals; no allocation allowed) ----------------
__device__ float g_q[(size_t)NT * DIM];
__device__ __nv_bfloat16 g_kvb[(size_t)NT * 256];   // k at +0, v at +128 (bf16)
__device__ float g_h[(size_t)NT * DIM];      // skip -> +agg+LN+relu in place
__device__ int g_dcnt[NT];
__device__ int g_rowptr[NT + 1];
__device__ int g_cursor[NT];
__device__ int g_col[ET];
__device__ int g_bsum[NBLK];
__device__ int g_bex[NBLK];
// W^T bf16 hi/lo images: [matrix 0..3][n 0..127][k 0..127]
__device__ __align__(16) __nv_bfloat16 g_wt_hi[4 * 128 * 128];
__device__ __align__(16) __nv_bfloat16 g_wt_lo[4 * 128 * 128];
// bias rows: [matrix][128]
__device__ __align__(16) float g_brow[4 * 128];

// ---------------- helpers ----------------
__device__ __forceinline__ float warp_sum(float v) {
    #pragma unroll
    for (int o = 16; o; o >>= 1) v += __shfl_xor_sync(0xffffffffu, v, o);
    return v;
}
__device__ __forceinline__ uint32_t smem_u32(const void* p) {
    uint32_t a;
    asm("{ .reg .u64 t; cvta.to.shared.u64 t, %1; cvt.u32.u64 %0, t; }"
        : "=r"(a) : "l"(p));
    return a;
}
__device__ __forceinline__ void cp_async16(uint32_t dst, const void* src) {
    asm volatile("cp.async.cg.shared.global [%0], [%1], 16;" :: "r"(dst), "l"(src));
}
__device__ __forceinline__ float4 bf8_to_f4(uint2 raw) {
    __nv_bfloat162 b0 = ((const __nv_bfloat162*)&raw)[0];
    __nv_bfloat162 b1 = ((const __nv_bfloat162*)&raw)[1];
    float2 f0 = __bfloat1622float2(b0);
    float2 f1 = __bfloat1622float2(b1);
    return make_float4(f0.x, f0.y, f1.x, f1.y);
}

// ---------------- K0a: prep weights -> W^T bf16 hi/lo ----------------
__global__ void prep_w(const float* __restrict__ Wq, const float* __restrict__ Wk,
                       const float* __restrict__ Wv, const float* __restrict__ Ws)
{
    int idx = blockIdx.x * 256 + threadIdx.x;  // 0..65535
    int m = idx >> 14;       // matrix 0..3
    int n = (idx >> 7) & 127;
    int k = idx & 127;
    const float* W = (m == 0) ? Wq : (m == 1) ? Wk : (m == 2) ? Wv : Ws;
    float w = W[k * 128 + n];
    __nv_bfloat16 hi = __float2bfloat16(w);
    __nv_bfloat16 lo = __float2bfloat16(w - __bfloat162float(hi));
    g_wt_hi[idx] = hi;
    g_wt_lo[idx] = lo;
}

// ---------------- K0b: prep bias rows ----------------
__global__ void prep_b(const float* __restrict__ bq, const float* __restrict__ bk,
                       const float* __restrict__ bv, const float* __restrict__ bs)
{
    int idx = blockIdx.x * 256 + threadIdx.x;  // 0..511
    int m = idx >> 7;
    int n = idx & 127;
    const float* B = (m == 0) ? bq : (m == 1) ? bk : (m == 2) ? bv : bs;
    g_brow[idx] = B[n];
}

// ---------------- K1: fused QKV+skip GEMM via HMMA (bf16x3, cp.async, 16 warps) ----------------
// SMEM (bf16 elems): A_hi, A_lo, Bbuf0{hi,lo}, Bbuf1{hi,lo}, then 8KB fp32 bias tile
#define LDA 136
#define A_ELEMS (128 * LDA)            /* 17408 */
#define SM_ALO  A_ELEMS
#define SM_B0   (2 * A_ELEMS)          /* 34816 */
#define SM_B1   (SM_B0 + 2 * A_ELEMS)  /* 69632 */
#define SM_BIAS_ELEMS (SM_B1 + 2 * A_ELEMS)   /* 104448 bf16 elems */
#define SM_BYTES (SM_BIAS_ELEMS * 2 + 16 * 128 * 4)  /* 208896 + 8192 = 217088 */
#define LDS_STAGE 132                  /* f32 staging stride (128x132x4 = 67584 <= 69632) */

__global__ void __launch_bounds__(512, 1)
gemm_hmma(const float* __restrict__ xh, const float* __restrict__ xl)
{
    extern __shared__ __nv_bfloat16 sm[];
    float* bias_s = (float*)(sm + SM_BIAS_ELEMS);   // 16 x 128 fp32
    const uint32_t sbase = smem_u32(sm);
    const int t = threadIdx.x;
    const int wid = t >> 5;
    const int wm = wid & 3;        // warp row group: 32 rows each
    const int wn = wid >> 2;       // warp col group: 32 cols each

    // issue B prefetch for m=0 into buf0 (before A conversion, to overlap)
    {
        const uint4* ghi = (const uint4*)(g_wt_hi);
        const uint4* glo = (const uint4*)(g_wt_lo);
        uint32_t bhi = sbase + SM_B0 * 2;
        uint32_t blo = sbase + (SM_B0 + A_ELEMS) * 2;
        #pragma unroll
        for (int j = 0; j < 4; j++) {
            int idx = t + 512 * j;      // 0..2047 (16B chunks)
            int n = idx >> 4;
            int c = idx & 15;
            uint32_t off = (uint32_t)(n * LDA + c * 8) * 2;
            cp_async16(bhi + off, ghi + idx);
            cp_async16(blo + off, glo + idx);
        }
        asm volatile("cp.async.commit_group;");
    }

    // ---- load + split-convert A tile (128 rows x 128 k) ----
    const int row0 = blockIdx.x * 128;
    const float* X = (row0 < NHI) ? (xh + (size_t)row0 * DIM)
                                  : (xl + (size_t)(row0 - NHI) * DIM);
    #pragma unroll
    for (int j = 0; j < 8; j++) {
        int v = t + 512 * j;            // float4 index 0..4095
        int r = v >> 5;                 // row 0..127
        int k0 = (v & 31) * 4;          // k 0..124
        float4 x = ((const float4*)X)[v];
        float xs[4] = {x.x, x.y, x.z, x.w};
        unsigned short h[4], l[4];
        #pragma unroll
        for (int i = 0; i < 4; i++) {
            __nv_bfloat16 bh = __float2bfloat16(xs[i]);
            __nv_bfloat16 bl = __float2bfloat16(xs[i] - __bfloat162float(bh));
            h[i] = *(unsigned short*)&bh;
            l[i] = *(unsigned short*)&bl;
        }
        uint2 hv = make_uint2((uint32_t)h[0] | ((uint32_t)h[1] << 16),
                              (uint32_t)h[2] | ((uint32_t)h[3] << 16));
        uint2 lv = make_uint2((uint32_t)l[0] | ((uint32_t)l[1] << 16),
                              (uint32_t)l[2] | ((uint32_t)l[3] << 16));
        *(uint2*)(sm + r * LDA + k0)          = hv;
        *(uint2*)(sm + SM_ALO + r * LDA + k0) = lv;
    }

    #pragma unroll
    for (int m = 0; m < 4; m++) {
        // issue prefetch for m+1 into the other buffer
        if (m < 3) {
            const uint4* ghi = (const uint4*)(g_wt_hi + (m + 1) * 128 * 128);
            const uint4* glo = (const uint4*)(g_wt_lo + (m + 1) * 128 * 128);
            int bsel = (m + 1) & 1;
            uint32_t bhi = sbase + (bsel ? SM_B1 : SM_B0) * 2;
            uint32_t blo = bhi + A_ELEMS * 2;
            #pragma unroll
            for (int j = 0; j < 4; j++) {
                int idx = t + 512 * j;
                int n = idx >> 4;
                int c = idx & 15;
                uint32_t off = (uint32_t)(n * LDA + c * 8) * 2;
                cp_async16(bhi + off, ghi + idx);
                cp_async16(blo + off, glo + idx);
            }
            asm volatile("cp.async.commit_group;");
            asm volatile("cp.async.wait_group 1;");
        } else {
            asm volatile("cp.async.wait_group 0;");
        }
        // stage bias rows (16 identical rows) into smem for acc init
        {
            float b = g_brow[m * 128 + (t & 127)];
            #pragma unroll
            for (int r = t >> 7; r < 16; r += 4)
                bias_s[r * 128 + (t & 127)] = b;
        }
        __syncthreads();   // B[m]+bias ready; prior phase readers done

        __nv_bfloat16* Bbuf = sm + ((m & 1) ? SM_B1 : SM_B0);
        const __nv_bfloat16* Bhi = Bbuf;
        const __nv_bfloat16* Blo = Bbuf + A_ELEMS;

        wmma::fragment<wmma::accumulator, 16, 16, 16, float> acc[2][2];
        #pragma unroll
        for (int i = 0; i < 2; i++)
            #pragma unroll
            for (int j = 0; j < 2; j++)
                wmma::load_matrix_sync(acc[i][j],
                    bias_s + wn * 32 + j * 16, 128, wmma::mem_row_major);

        #pragma unroll
        for (int ks = 0; ks < 8; ks++) {
            wmma::fragment<wmma::matrix_a, 16, 16, 16, __nv_bfloat16, wmma::row_major> ah[2], al[2];
            wmma::fragment<wmma::matrix_b, 16, 16, 16, __nv_bfloat16, wmma::col_major> bh[2], bl[2];
            #pragma unroll
            for (int i = 0; i < 2; i++) {
                int r = wm * 32 + i * 16;
                wmma::load_matrix_sync(ah[i], sm + r * LDA + ks * 16, LDA);
                wmma::load_matrix_sync(al[i], sm + SM_ALO + r * LDA + ks * 16, LDA);
            }
            #pragma unroll
            for (int j = 0; j < 2; j++) {
                int n = wn * 32 + j * 16;
                wmma::load_matrix_sync(bh[j], Bhi + n * LDA + ks * 16, LDA);
                wmma::load_matrix_sync(bl[j], Blo + n * LDA + ks * 16, LDA);
            }
            #pragma unroll
            for (int i = 0; i < 2; i++)
                #pragma unroll
                for (int j = 0; j < 2; j++) {
                    wmma::mma_sync(acc[i][j], ah[i], bh[j], acc[i][j]);
                    wmma::mma_sync(acc[i][j], al[i], bh[j], acc[i][j]);
                    wmma::mma_sync(acc[i][j], ah[i], bl[j], acc[i][j]);
                }
        }

        if (m == 0 || m == 3) {
            // q / h: direct f32 store
            float* O = ((m == 0) ? g_q : g_h) + (size_t)row0 * DIM;
            #pragma unroll
            for (int i = 0; i < 2; i++)
                #pragma unroll
                for (int j = 0; j < 2; j++)
                    wmma::store_matrix_sync(
                        O + (size_t)(wm * 32 + i * 16) * DIM + wn * 32 + j * 16,
                        acc[i][j], DIM, wmma::mem_row_major);
        } else {
            // k / v: stage f32 in the just-consumed B buffer, convert to bf16, store
            __syncthreads();   // all warps done reading B[m] before we overwrite it
            float* stage = (float*)Bbuf;
            #pragma unroll
            for (int i = 0; i < 2; i++)
                #pragma unroll
                for (int j = 0; j < 2; j++)
                    wmma::store_matrix_sync(
                        stage + (wm * 32 + i * 16) * LDS_STAGE + wn * 32 + j * 16,
                        acc[i][j], LDS_STAGE, wmma::mem_row_major);
            __syncthreads();
            __nv_bfloat16* dst = g_kvb + (size_t)row0 * 256 + ((m == 1) ? 0 : 128);
            #pragma unroll
            for (int j = 0; j < 8; j++) {
                int v = t + 512 * j;        // 0..4095
                int r = v >> 5;
                int c = (v & 31) * 4;
                float4 x = *(const float4*)(stage + r * LDS_STAGE + c);
                __nv_bfloat162 p0 = __floats2bfloat162_rn(x.x, x.y);
                __nv_bfloat162 p1 = __floats2bfloat162_rn(x.z, x.w);
                uint2 o = make_uint2(*(uint32_t*)&p0, *(uint32_t*)&p1);
                *(uint2*)(dst + (size_t)r * 256 + c) = o;
            }
        }
        __syncthreads();   // phase barrier: B buffer/staging free before next prefetch
    }
}

// ---------------- CSR build ----------------
__global__ void edge_hist(const int* __restrict__ eih, const int* __restrict__ eil)
{
    int e = blockIdx.x * 256 + threadIdx.x;
    if (e >= ET) return;
    int dst = (e < EHI) ? eih[EHI + e] : (eil[ELO + (e - EHI)] + NHI);
    atomicAdd(&g_dcnt[dst], 1);
}

__global__ void scan_local()
{
    __shared__ int sh[1024];
    const int t = threadIdx.x;
    const int i = blockIdx.x * 1024 + t;
    int v = g_dcnt[i];
    sh[t] = v;
    __syncthreads();
    #pragma unroll
    for (int off = 1; off < 1024; off <<= 1) {
        int u = (t >= off) ? sh[t - off] : 0;
        __syncthreads();
        sh[t] += u;
        __syncthreads();
    }
    g_rowptr[i] = sh[t] - v;            // local exclusive
    if (t == 1023) g_bsum[blockIdx.x] = sh[t];
}

__global__ void scan_bsum()
{
    __shared__ int sh[512];
    const int t = threadIdx.x;          // 512 threads
    int v = (t < NBLK) ? g_bsum[t] : 0;
    sh[t] = v;
    __syncthreads();
    #pragma unroll
    for (int off = 1; off < 512; off <<= 1) {
        int u = (t >= off) ? sh[t - off] : 0;
        __syncthreads();
        sh[t] += u;
        __syncthreads();
    }
    if (t < NBLK) g_bex[t] = sh[t] - v; // exclusive block base
    if (t == 511) g_rowptr[NT] = sh[511];
}

__global__ void scan_add()
{
    const int i = blockIdx.x * 1024 + threadIdx.x;
    int r = g_rowptr[i] + g_bex[blockIdx.x];
    g_rowptr[i] = r;
    g_cursor[i] = r;
}

__global__ void edge_scatter(const int* __restrict__ eih, const int* __restrict__ eil)
{
    int e = blockIdx.x * 256 + threadIdx.x;
    if (e >= ET) return;
    int src, dst;
    if (e < EHI) { src = eih[e];             dst = eih[EHI + e]; }
    else         { src = eil[e - EHI] + NHI; dst = eil[ELO + (e - EHI)] + NHI; }
    int pos = atomicAdd(&g_cursor[dst], 1);
    g_col[pos] = src;
}

// ---------------- K2: one-pass attention (online softmax) + fused LN/ReLU ----------------
// lane owns 4 contiguous columns [lane*4, lane*4+4); head = lane>>3.
__global__ void __launch_bounds__(256)
attn_ln(const float* __restrict__ lnw, const float* __restrict__ lnb)
{
    int node = blockIdx.x * 8 + threadIdx.y;
    int lane = threadIdx.x;
    int s = g_rowptr[node];
    int e1 = g_rowptr[node + 1];

    float* hr = g_h + (size_t)node * DIM;
    float4 val = ((float4*)hr)[lane];   // skip term

    if (s < e1) {
        float4 qv = ((const float4*)(g_q + (size_t)node * DIM))[lane];

        float m = -INFINITY, d = 0.f;
        float4 acc = make_float4(0.f, 0.f, 0.f, 0.f);

        // 1-deep software pipeline on the kv gather (512B contiguous per edge)
        const uint2* kvp = (const uint2*)(g_kvb + (size_t)g_col[s] * 256);
        uint2 kraw = kvp[lane];
        uint2 vraw = kvp[lane + 32];
        for (int i = s; i < e1; i++) {
            float4 kc = bf8_to_f4(kraw);
            float4 vc = bf8_to_f4(vraw);
            if (i + 1 < e1) {
                const uint2* np = (const uint2*)(g_kvb + (size_t)g_col[i + 1] * 256);
                kraw = np[lane];
                vraw = np[lane + 32];
            }
            // per-lane partial dot over its 4 cols, butterfly within 8-lane head group
            float p = qv.x * kc.x + qv.y * kc.y + qv.z * kc.z + qv.w * kc.w;
            p += __shfl_xor_sync(0xffffffffu, p, 4);
            p += __shfl_xor_sync(0xffffffffu, p, 2);
            p += __shfl_xor_sync(0xffffffffu, p, 1);
            float sc = p * SCALE;            // this lane's head score
            float mn = fmaxf(m, sc);
            float c = __expf(m - mn);        // 0 when m was -inf
            float w = __expf(sc - mn);
            d = d * c + w;
            acc.x = acc.x * c + w * vc.x;
            acc.y = acc.y * c + w * vc.y;
            acc.z = acc.z * c + w * vc.z;
            acc.w = acc.w * c + w * vc.w;
            m = mn;
        }
        float inv = 1.0f / d;
        val.x += acc.x * inv;
        val.y += acc.y * inv;
        val.z += acc.z * inv;
        val.w += acc.w * inv;
    }

    // fused LayerNorm + ReLU (warp holds the full 128-dim row)
    float sum = warp_sum(val.x + val.y + val.z + val.w);
    float sq = warp_sum(val.x * val.x + val.y * val.y + val.z * val.z + val.w * val.w);
    float mean = sum * (1.0f / 128.0f);
    float var = sq * (1.0f / 128.0f) - mean * mean;
    float rstd = rsqrtf(var + 1e-5f);
    float4 w4 = ((const float4*)lnw)[lane];
    float4 b4 = ((const float4*)lnb)[lane];
    float4 o;
    o.x = fmaxf((val.x - mean) * rstd * w4.x + b4.x, 0.0f);
    o.y = fmaxf((val.y - mean) * rstd * w4.y + b4.y, 0.0f);
    o.z = fmaxf((val.z - mean) * rstd * w4.z + b4.z, 0.0f);
    o.w = fmaxf((val.w - mean) * rstd * w4.w + b4.w, 0.0f);
    ((float4*)hr)[lane] = o;
}

// ---------------- K3: segmented pool + high-node gating (one warp per high node) ----------------
__device__ __forceinline__ int lower_bound_batch(const int* __restrict__ batch, int key)
{
    int lo = 0, hi = NLO;
    while (lo < hi) {
        int mid = (lo + hi) >> 1;
        if (batch[mid] < key) lo = mid + 1; else hi = mid;
    }
    return lo;
}

__global__ void __launch_bounds__(256)
pool_final_high(const int* __restrict__ batch, const float* __restrict__ wlh,
                float* __restrict__ out)
{
    int g = blockIdx.x * 8 + threadIdx.y;
    int lane = threadIdx.x;
    int lb = lower_bound_batch(batch, g);
    int ub = lower_bound_batch(batch, g + 1);

    float4 s = make_float4(0.f, 0.f, 0.f, 0.f);
    for (int j = lb; j < ub; j++) {
        float4 lr = ((const float4*)(g_h + (size_t)(NHI + j) * DIM))[lane];
        s.x += lr.x; s.y += lr.y; s.z += lr.z; s.w += lr.w;
    }
    float inv = 1.0f / fmaxf((float)(ub - lb), 1.0f);
    float4 pv = make_float4(s.x * inv, s.y * inv, s.z * inv, s.w * inv);

    float4 hv = ((const float4*)(g_h + (size_t)g * DIM))[lane];
    float4 w0 = ((const float4*)wlh)[lane];
    float4 w1 = ((const float4*)(wlh + DIM))[lane];
    float dot = hv.x * w0.x + hv.y * w0.y + hv.z * w0.z + hv.w * w0.w
              + pv.x * w1.x + pv.y * w1.y + pv.z * w1.z + pv.w * w1.w;
    dot = warp_sum(dot);
    float sgm = 1.0f / (1.0f + __expf(-dot));
    float4 o;
    o.x = sgm * hv.x + (1.0f - sgm) * pv.x;
    o.y = sgm * hv.y + (1.0f - sgm) * pv.y;
    o.z = sgm * hv.z + (1.0f - sgm) * pv.z;
    o.w = sgm * hv.w + (1.0f - sgm) * pv.w;
    ((float4*)(out + (size_t)g * DIM))[lane] = o;
}

// ---------------- K4: low-node gating epilogue ----------------
__global__ void final_low(const float* __restrict__ whl, const int* __restrict__ batch,
                          float* __restrict__ out)
{
    int j = blockIdx.x * 8 + threadIdx.y;
    int lane = threadIdx.x;
    int g = batch[j];
    float4 hb = ((const float4*)(g_h + (size_t)g * DIM))[lane];
    float4 lv = ((const float4*)(g_h + (size_t)(NHI + j) * DIM))[lane];
    float4 w0 = ((const float4*)whl)[lane];
    float4 w1 = ((const float4*)(whl + DIM))[lane];
    float d = hb.x * w0.x + hb.y * w0.y + hb.z * w0.z + hb.w * w0.w
            + lv.x * w1.x + lv.y * w1.y + lv.z * w1.z + lv.w * w1.w;
    d = warp_sum(d);
    float a = 1.0f / (1.0f + __expf(-d));
    float4 o;
    o.x = a * lv.x + (1.0f - a) * hb.x;
    o.y = a * lv.y + (1.0f - a) * hb.y;
    o.z = a * lv.z + (1.0f - a) * hb.z;
    o.w = a * lv.w + (1.0f - a) * hb.w;
    ((float4*)(out + (size_t)j * DIM))[lane] = o;
}

// ---------------- launch ----------------
extern "C" void kernel_launch(void* const* d_in, const int* in_sizes, int n_in,
                              void* d_out, int out_size)
{
    const float* high_emb = (const float*)d_in[0];
    const float* low_emb  = (const float*)d_in[1];
    const float* Wq = (const float*)d_in[2];  const float* bq = (const float*)d_in[3];
    const float* Wk = (const float*)d_in[4];  const float* bk = (const float*)d_in[5];
    const float* Wv = (const float*)d_in[6];  const float* bv = (const float*)d_in[7];
    const float* Ws = (const float*)d_in[8];  const float* bs = (const float*)d_in[9];
    const float* lnw = (const float*)d_in[10];
    const float* lnb = (const float*)d_in[11];
    const float* wlh = (const float*)d_in[12];
    const float* whl = (const float*)d_in[13];
    const int* eih   = (const int*)d_in[14];
    const int* eil   = (const int*)d_in[15];
    const int* batch = (const int*)d_in[16];
    float* out = (float*)d_out;

    void* pcnt;
    cudaGetSymbolAddress(&pcnt, g_dcnt);
    cudaMemsetAsync(pcnt, 0, NT * sizeof(int), 0);

    cudaFuncSetAttribute(gemm_hmma, cudaFuncAttributeMaxDynamicSharedMemorySize, SM_BYTES);

    // launch order keeps gemm_hmma at the profiled slot
    prep_w<<<256, 256>>>(Wq, Wk, Wv, Ws);                       // 1
    prep_b<<<2, 256>>>(bq, bk, bv, bs);                         // 2
    edge_hist<<<(ET + 255) / 256, 256>>>(eih, eil);             // 3
    gemm_hmma<<<NT / 128, 512, SM_BYTES>>>(high_emb, low_emb);  // 4  <- profiled

    scan_local<<<NBLK, 1024>>>();
    scan_bsum<<<1, 512>>>();
    scan_add<<<NBLK, 1024>>>();
    edge_scatter<<<(ET + 255) / 256, 256>>>(eih, eil);

    dim3 t32x8(32, 8);
    attn_ln<<<NT / 8, t32x8>>>(lnw, lnb);
    pool_final_high<<<NHI / 8, t32x8>>>(batch, wlh, out);
    final_low<<<NLO / 8, t32x8>>>(whl, batch, out + (size_t)NHI * DIM);
}

// round 10
// speedup vs baseline: 1.9773x; 1.0545x over previous
#include <cuda_runtime.h>
#include <cuda_bf16.h>
#include <cuda_fp16.h>
#include <mma.h>
#include <math.h>
#include <cstdint>

using namespace nvcuda;

#define NHI 4096
#define NLO 262144
#define NT  (NHI + NLO)      /* 266240 = 260 * 1024 */
#define EHI 65536
#define ELO 524288
#define ET  (EHI + ELO)
#define DIM 128
#define NHEAD 4
#define HDIM 32
#define SCALE 0.17677669529663687f   /* 1/sqrt(32) */
#define NBLK 260             /* scan blocks */

// ---------------- scratch (device globals; no allocation allowed) ----------------
__device__ float g_q[(size_t)NT * DIM];
__device__ __half g_kvh[(size_t)NT * 256];   // k at +0, v at +128 (fp16)
__device__ float g_h[(size_t)NT * DIM];      // skip -> +agg+LN+relu in place
__device__ int g_dcnt[NT];
__device__ int g_rowptr[NT + 1];
__device__ int g_cursor[NT];
__device__ int g_col[ET];
__device__ int g_bsum[NBLK];
__device__ int g_bex[NBLK];
// W^T bf16 hi/lo images: [matrix 0..3][n 0..127][k 0..127]
__device__ __align__(16) __nv_bfloat16 g_wt_hi[4 * 128 * 128];
__device__ __align__(16) __nv_bfloat16 g_wt_lo[4 * 128 * 128];
// bias rows: [matrix][128]
__device__ __align__(16) float g_brow[4 * 128];

// ---------------- helpers ----------------
__device__ __forceinline__ float warp_sum(float v) {
    #pragma unroll
    for (int o = 16; o; o >>= 1) v += __shfl_xor_sync(0xffffffffu, v, o);
    return v;
}
__device__ __forceinline__ uint32_t smem_u32(const void* p) {
    uint32_t a;
    asm("{ .reg .u64 t; cvta.to.shared.u64 t, %1; cvt.u32.u64 %0, t; }"
        : "=r"(a) : "l"(p));
    return a;
}
__device__ __forceinline__ void cp_async16(uint32_t dst, const void* src) {
    asm volatile("cp.async.cg.shared.global [%0], [%1], 16;" :: "r"(dst), "l"(src));
}
__device__ __forceinline__ float4 hf8_to_f4(uint2 raw) {
    __half2 h0 = ((const __half2*)&raw)[0];
    __half2 h1 = ((const __half2*)&raw)[1];
    float2 f0 = __half22float2(h0);
    float2 f1 = __half22float2(h1);
    return make_float4(f0.x, f0.y, f1.x, f1.y);
}

// ---------------- K0a: prep weights -> W^T bf16 hi/lo ----------------
__global__ void prep_w(const float* __restrict__ Wq, const float* __restrict__ Wk,
                       const float* __restrict__ Wv, const float* __restrict__ Ws)
{
    int idx = blockIdx.x * 256 + threadIdx.x;  // 0..65535
    int m = idx >> 14;       // matrix 0..3
    int n = (idx >> 7) & 127;
    int k = idx & 127;
    const float* W = (m == 0) ? Wq : (m == 1) ? Wk : (m == 2) ? Wv : Ws;
    float w = W[k * 128 + n];
    __nv_bfloat16 hi = __float2bfloat16(w);
    __nv_bfloat16 lo = __float2bfloat16(w - __bfloat162float(hi));
    g_wt_hi[idx] = hi;
    g_wt_lo[idx] = lo;
}

// ---------------- K0b: prep bias rows ----------------
__global__ void prep_b(const float* __restrict__ bq, const float* __restrict__ bk,
                       const float* __restrict__ bv, const float* __restrict__ bs)
{
    int idx = blockIdx.x * 256 + threadIdx.x;  // 0..511
    int m = idx >> 7;
    int n = idx & 127;
    const float* B = (m == 0) ? bq : (m == 1) ? bk : (m == 2) ? bv : bs;
    g_brow[idx] = B[n];
}

// ---------------- K1: fused QKV+skip GEMM via HMMA (bf16x3, cp.async, 16 warps) ----------------
// SMEM (bf16 elems): A_hi, A_lo, Bbuf0{hi,lo}, Bbuf1{hi,lo}, then 8KB fp32 bias tile
#define LDA 136
#define A_ELEMS (128 * LDA)            /* 17408 */
#define SM_ALO  A_ELEMS
#define SM_B0   (2 * A_ELEMS)          /* 34816 */
#define SM_B1   (SM_B0 + 2 * A_ELEMS)  /* 69632 */
#define SM_BIAS_ELEMS (SM_B1 + 2 * A_ELEMS)   /* 104448 bf16 elems */
#define SM_BYTES (SM_BIAS_ELEMS * 2 + 16 * 128 * 4)  /* 208896 + 8192 = 217088 */
#define LDS_STAGE 132                  /* f32 staging stride (128x132x4 = 67584 <= 69632) */

__global__ void __launch_bounds__(512, 1)
gemm_hmma(const float* __restrict__ xh, const float* __restrict__ xl)
{
    extern __shared__ __nv_bfloat16 sm[];
    float* bias_s = (float*)(sm + SM_BIAS_ELEMS);   // 16 x 128 fp32
    const uint32_t sbase = smem_u32(sm);
    const int t = threadIdx.x;
    const int wid = t >> 5;
    const int wm = wid & 3;        // warp row group: 32 rows each
    const int wn = wid >> 2;       // warp col group: 32 cols each

    // issue B prefetch for m=0 into buf0 (before A conversion, to overlap)
    {
        const uint4* ghi = (const uint4*)(g_wt_hi);
        const uint4* glo = (const uint4*)(g_wt_lo);
        uint32_t bhi = sbase + SM_B0 * 2;
        uint32_t blo = sbase + (SM_B0 + A_ELEMS) * 2;
        #pragma unroll
        for (int j = 0; j < 4; j++) {
            int idx = t + 512 * j;      // 0..2047 (16B chunks)
            int n = idx >> 4;
            int c = idx & 15;
            uint32_t off = (uint32_t)(n * LDA + c * 8) * 2;
            cp_async16(bhi + off, ghi + idx);
            cp_async16(blo + off, glo + idx);
        }
        asm volatile("cp.async.commit_group;");
    }

    // ---- load + split-convert A tile (128 rows x 128 k) ----
    const int row0 = blockIdx.x * 128;
    const float* X = (row0 < NHI) ? (xh + (size_t)row0 * DIM)
                                  : (xl + (size_t)(row0 - NHI) * DIM);
    #pragma unroll
    for (int j = 0; j < 8; j++) {
        int v = t + 512 * j;            // float4 index 0..4095
        int r = v >> 5;                 // row 0..127
        int k0 = (v & 31) * 4;          // k 0..124
        float4 x = ((const float4*)X)[v];
        float xs[4] = {x.x, x.y, x.z, x.w};
        unsigned short h[4], l[4];
        #pragma unroll
        for (int i = 0; i < 4; i++) {
            __nv_bfloat16 bh = __float2bfloat16(xs[i]);
            __nv_bfloat16 bl = __float2bfloat16(xs[i] - __bfloat162float(bh));
            h[i] = *(unsigned short*)&bh;
            l[i] = *(unsigned short*)&bl;
        }
        uint2 hv = make_uint2((uint32_t)h[0] | ((uint32_t)h[1] << 16),
                              (uint32_t)h[2] | ((uint32_t)h[3] << 16));
        uint2 lv = make_uint2((uint32_t)l[0] | ((uint32_t)l[1] << 16),
                              (uint32_t)l[2] | ((uint32_t)l[3] << 16));
        *(uint2*)(sm + r * LDA + k0)          = hv;
        *(uint2*)(sm + SM_ALO + r * LDA + k0) = lv;
    }

    #pragma unroll
    for (int m = 0; m < 4; m++) {
        // issue prefetch for m+1 into the other buffer
        if (m < 3) {
            const uint4* ghi = (const uint4*)(g_wt_hi + (m + 1) * 128 * 128);
            const uint4* glo = (const uint4*)(g_wt_lo + (m + 1) * 128 * 128);
            int bsel = (m + 1) & 1;
            uint32_t bhi = sbase + (bsel ? SM_B1 : SM_B0) * 2;
            uint32_t blo = bhi + A_ELEMS * 2;
            #pragma unroll
            for (int j = 0; j < 4; j++) {
                int idx = t + 512 * j;
                int n = idx >> 4;
                int c = idx & 15;
                uint32_t off = (uint32_t)(n * LDA + c * 8) * 2;
                cp_async16(bhi + off, ghi + idx);
                cp_async16(blo + off, glo + idx);
            }
            asm volatile("cp.async.commit_group;");
            asm volatile("cp.async.wait_group 1;");
        } else {
            asm volatile("cp.async.wait_group 0;");
        }
        // stage bias rows (16 identical rows) into smem for acc init
        {
            float b = g_brow[m * 128 + (t & 127)];
            #pragma unroll
            for (int r = t >> 7; r < 16; r += 4)
                bias_s[r * 128 + (t & 127)] = b;
        }
        __syncthreads();   // B[m]+bias ready; prior phase readers done

        __nv_bfloat16* Bbuf = sm + ((m & 1) ? SM_B1 : SM_B0);
        const __nv_bfloat16* Bhi = Bbuf;
        const __nv_bfloat16* Blo = Bbuf + A_ELEMS;

        wmma::fragment<wmma::accumulator, 16, 16, 16, float> acc[2][2];
        #pragma unroll
        for (int i = 0; i < 2; i++)
            #pragma unroll
            for (int j = 0; j < 2; j++)
                wmma::load_matrix_sync(acc[i][j],
                    bias_s + wn * 32 + j * 16, 128, wmma::mem_row_major);

        #pragma unroll
        for (int ks = 0; ks < 8; ks++) {
            wmma::fragment<wmma::matrix_a, 16, 16, 16, __nv_bfloat16, wmma::row_major> ah[2], al[2];
            wmma::fragment<wmma::matrix_b, 16, 16, 16, __nv_bfloat16, wmma::col_major> bh[2], bl[2];
            #pragma unroll
            for (int i = 0; i < 2; i++) {
                int r = wm * 32 + i * 16;
                wmma::load_matrix_sync(ah[i], sm + r * LDA + ks * 16, LDA);
                wmma::load_matrix_sync(al[i], sm + SM_ALO + r * LDA + ks * 16, LDA);
            }
            #pragma unroll
            for (int j = 0; j < 2; j++) {
                int n = wn * 32 + j * 16;
                wmma::load_matrix_sync(bh[j], Bhi + n * LDA + ks * 16, LDA);
                wmma::load_matrix_sync(bl[j], Blo + n * LDA + ks * 16, LDA);
            }
            #pragma unroll
            for (int i = 0; i < 2; i++)
                #pragma unroll
                for (int j = 0; j < 2; j++) {
                    wmma::mma_sync(acc[i][j], ah[i], bh[j], acc[i][j]);
                    wmma::mma_sync(acc[i][j], al[i], bh[j], acc[i][j]);
                    wmma::mma_sync(acc[i][j], ah[i], bl[j], acc[i][j]);
                }
        }

        if (m == 0 || m == 3) {
            // q / h: direct f32 store
            float* O = ((m == 0) ? g_q : g_h) + (size_t)row0 * DIM;
            #pragma unroll
            for (int i = 0; i < 2; i++)
                #pragma unroll
                for (int j = 0; j < 2; j++)
                    wmma::store_matrix_sync(
                        O + (size_t)(wm * 32 + i * 16) * DIM + wn * 32 + j * 16,
                        acc[i][j], DIM, wmma::mem_row_major);
        } else {
            // k / v: stage f32 in the just-consumed B buffer, convert to fp16, store
            __syncthreads();   // all warps done reading B[m] before we overwrite it
            float* stage = (float*)Bbuf;
            #pragma unroll
            for (int i = 0; i < 2; i++)
                #pragma unroll
                for (int j = 0; j < 2; j++)
                    wmma::store_matrix_sync(
                        stage + (wm * 32 + i * 16) * LDS_STAGE + wn * 32 + j * 16,
                        acc[i][j], LDS_STAGE, wmma::mem_row_major);
            __syncthreads();
            __half* dst = g_kvh + (size_t)row0 * 256 + ((m == 1) ? 0 : 128);
            #pragma unroll
            for (int j = 0; j < 8; j++) {
                int v = t + 512 * j;        // 0..4095
                int r = v >> 5;
                int c = (v & 31) * 4;
                float4 x = *(const float4*)(stage + r * LDS_STAGE + c);
                __half2 p0 = __floats2half2_rn(x.x, x.y);
                __half2 p1 = __floats2half2_rn(x.z, x.w);
                uint2 o = make_uint2(*(uint32_t*)&p0, *(uint32_t*)&p1);
                *(uint2*)(dst + (size_t)r * 256 + c) = o;
            }
        }
        __syncthreads();   // phase barrier: B buffer/staging free before next prefetch
    }
}

// ---------------- CSR build ----------------
__global__ void edge_hist(const int* __restrict__ eih, const int* __restrict__ eil)
{
    int e = blockIdx.x * 256 + threadIdx.x;
    if (e >= ET) return;
    int dst = (e < EHI) ? eih[EHI + e] : (eil[ELO + (e - EHI)] + NHI);
    atomicAdd(&g_dcnt[dst], 1);
}

__global__ void scan_local()
{
    __shared__ int sh[1024];
    const int t = threadIdx.x;
    const int i = blockIdx.x * 1024 + t;
    int v = g_dcnt[i];
    sh[t] = v;
    __syncthreads();
    #pragma unroll
    for (int off = 1; off < 1024; off <<= 1) {
        int u = (t >= off) ? sh[t - off] : 0;
        __syncthreads();
        sh[t] += u;
        __syncthreads();
    }
    g_rowptr[i] = sh[t] - v;            // local exclusive
    if (t == 1023) g_bsum[blockIdx.x] = sh[t];
}

__global__ void scan_bsum()
{
    __shared__ int sh[512];
    const int t = threadIdx.x;          // 512 threads
    int v = (t < NBLK) ? g_bsum[t] : 0;
    sh[t] = v;
    __syncthreads();
    #pragma unroll
    for (int off = 1; off < 512; off <<= 1) {
        int u = (t >= off) ? sh[t - off] : 0;
        __syncthreads();
        sh[t] += u;
        __syncthreads();
    }
    if (t < NBLK) g_bex[t] = sh[t] - v; // exclusive block base
    if (t == 511) g_rowptr[NT] = sh[511];
}

__global__ void scan_add()
{
    const int i = blockIdx.x * 1024 + threadIdx.x;
    int r = g_rowptr[i] + g_bex[blockIdx.x];
    g_rowptr[i] = r;
    g_cursor[i] = r;
}

__global__ void edge_scatter(const int* __restrict__ eih, const int* __restrict__ eil)
{
    int e = blockIdx.x * 256 + threadIdx.x;
    if (e >= ET) return;
    int src, dst;
    if (e < EHI) { src = eih[e];             dst = eih[EHI + e]; }
    else         { src = eil[e - EHI] + NHI; dst = eil[ELO + (e - EHI)] + NHI; }
    int pos = atomicAdd(&g_cursor[dst], 1);
    g_col[pos] = src;
}

// ---------------- K2: one-pass attention (online softmax) + fused LN/ReLU ----------------
// lane owns 4 contiguous columns [lane*4, lane*4+4); head = lane>>3.
__global__ void __launch_bounds__(256)
attn_ln(const float* __restrict__ lnw, const float* __restrict__ lnb)
{
    int node = blockIdx.x * 8 + threadIdx.y;
    int lane = threadIdx.x;
    int s = g_rowptr[node];
    int e1 = g_rowptr[node + 1];

    float* hr = g_h + (size_t)node * DIM;
    float4 val = ((float4*)hr)[lane];   // skip term

    if (s < e1) {
        float4 qv = ((const float4*)(g_q + (size_t)node * DIM))[lane];

        float m = -INFINITY, d = 0.f;
        float4 acc = make_float4(0.f, 0.f, 0.f, 0.f);

        // 1-deep software pipeline on the kv gather (512B contiguous per edge)
        const uint2* kvp = (const uint2*)(g_kvh + (size_t)g_col[s] * 256);
        uint2 kraw = kvp[lane];
        uint2 vraw = kvp[lane + 32];
        for (int i = s; i < e1; i++) {
            float4 kc = hf8_to_f4(kraw);
            float4 vc = hf8_to_f4(vraw);
            if (i + 1 < e1) {
                const uint2* np = (const uint2*)(g_kvh + (size_t)g_col[i + 1] * 256);
                kraw = np[lane];
                vraw = np[lane + 32];
            }
            // per-lane partial dot over its 4 cols, butterfly within 8-lane head group
            float p = qv.x * kc.x + qv.y * kc.y + qv.z * kc.z + qv.w * kc.w;
            p += __shfl_xor_sync(0xffffffffu, p, 4);
            p += __shfl_xor_sync(0xffffffffu, p, 2);
            p += __shfl_xor_sync(0xffffffffu, p, 1);
            float sc = p * SCALE;            // this lane's head score
            float mn = fmaxf(m, sc);
            float c = __expf(m - mn);        // 0 when m was -inf
            float w = __expf(sc - mn);
            d = d * c + w;
            acc.x = acc.x * c + w * vc.x;
            acc.y = acc.y * c + w * vc.y;
            acc.z = acc.z * c + w * vc.z;
            acc.w = acc.w * c + w * vc.w;
            m = mn;
        }
        float inv = 1.0f / d;
        val.x += acc.x * inv;
        val.y += acc.y * inv;
        val.z += acc.z * inv;
        val.w += acc.w * inv;
    }

    // fused LayerNorm + ReLU (warp holds the full 128-dim row)
    float sum = warp_sum(val.x + val.y + val.z + val.w);
    float sq = warp_sum(val.x * val.x + val.y * val.y + val.z * val.z + val.w * val.w);
    float mean = sum * (1.0f / 128.0f);
    float var = sq * (1.0f / 128.0f) - mean * mean;
    float rstd = rsqrtf(var + 1e-5f);
    float4 w4 = ((const float4*)lnw)[lane];
    float4 b4 = ((const float4*)lnb)[lane];
    float4 o;
    o.x = fmaxf((val.x - mean) * rstd * w4.x + b4.x, 0.0f);
    o.y = fmaxf((val.y - mean) * rstd * w4.y + b4.y, 0.0f);
    o.z = fmaxf((val.z - mean) * rstd * w4.z + b4.z, 0.0f);
    o.w = fmaxf((val.w - mean) * rstd * w4.w + b4.w, 0.0f);
    ((float4*)hr)[lane] = o;
}

// ---------------- K3: segmented pool + high-node gating (one warp per high node) ----------------
__device__ __forceinline__ int lower_bound_batch(const int* __restrict__ batch, int key)
{
    int lo = 0, hi = NLO;
    while (lo < hi) {
        int mid = (lo + hi) >> 1;
        if (batch[mid] < key) lo = mid + 1; else hi = mid;
    }
    return lo;
}

__global__ void __launch_bounds__(256)
pool_final_high(const int* __restrict__ batch, const float* __restrict__ wlh,
                float* __restrict__ out)
{
    int g = blockIdx.x * 8 + threadIdx.y;
    int lane = threadIdx.x;
    int lb = lower_bound_batch(batch, g);
    int ub = lower_bound_batch(batch, g + 1);

    float4 s = make_float4(0.f, 0.f, 0.f, 0.f);
    for (int j = lb; j < ub; j++) {
        float4 lr = ((const float4*)(g_h + (size_t)(NHI + j) * DIM))[lane];
        s.x += lr.x; s.y += lr.y; s.z += lr.z; s.w += lr.w;
    }
    float inv = 1.0f / fmaxf((float)(ub - lb), 1.0f);
    float4 pv = make_float4(s.x * inv, s.y * inv, s.z * inv, s.w * inv);

    float4 hv = ((const float4*)(g_h + (size_t)g * DIM))[lane];
    float4 w0 = ((const float4*)wlh)[lane];
    float4 w1 = ((const float4*)(wlh + DIM))[lane];
    float dot = hv.x * w0.x + hv.y * w0.y + hv.z * w0.z + hv.w * w0.w
              + pv.x * w1.x + pv.y * w1.y + pv.z * w1.z + pv.w * w1.w;
    dot = warp_sum(dot);
    float sgm = 1.0f / (1.0f + __expf(-dot));
    float4 o;
    o.x = sgm * hv.x + (1.0f - sgm) * pv.x;
    o.y = sgm * hv.y + (1.0f - sgm) * pv.y;
    o.z = sgm * hv.z + (1.0f - sgm) * pv.z;
    o.w = sgm * hv.w + (1.0f - sgm) * pv.w;
    ((float4*)(out + (size_t)g * DIM))[lane] = o;
}

// ---------------- K4: low-node gating epilogue ----------------
__global__ void final_low(const float* __restrict__ whl, const int* __restrict__ batch,
                          float* __restrict__ out)
{
    int j = blockIdx.x * 8 + threadIdx.y;
    int lane = threadIdx.x;
    int g = batch[j];
    float4 hb = ((const float4*)(g_h + (size_t)g * DIM))[lane];
    float4 lv = ((const float4*)(g_h + (size_t)(NHI + j) * DIM))[lane];
    float4 w0 = ((const float4*)whl)[lane];
    float4 w1 = ((const float4*)(whl + DIM))[lane];
    float d = hb.x * w0.x + hb.y * w0.y + hb.z * w0.z + hb.w * w0.w
            + lv.x * w1.x + lv.y * w1.y + lv.z * w1.z + lv.w * w1.w;
    d = warp_sum(d);
    float a = 1.0f / (1.0f + __expf(-d));
    float4 o;
    o.x = a * lv.x + (1.0f - a) * hb.x;
    o.y = a * lv.y + (1.0f - a) * hb.y;
    o.z = a * lv.z + (1.0f - a) * hb.z;
    o.w = a * lv.w + (1.0f - a) * hb.w;
    ((float4*)(out + (size_t)j * DIM))[lane] = o;
}

// ---------------- launch ----------------
extern "C" void kernel_launch(void* const* d_in, const int* in_sizes, int n_in,
                              void* d_out, int out_size)
{
    const float* high_emb = (const float*)d_in[0];
    const float* low_emb  = (const float*)d_in[1];
    const float* Wq = (const float*)d_in[2];  const float* bq = (const float*)d_in[3];
    const float* Wk = (const float*)d_in[4];  const float* bk = (const float*)d_in[5];
    const float* Wv = (const float*)d_in[6];  const float* bv = (const float*)d_in[7];
    const float* Ws = (const float*)d_in[8];  const float* bs = (const float*)d_in[9];
    const float* lnw = (const float*)d_in[10];
    const float* lnb = (const float*)d_in[11];
    const float* wlh = (const float*)d_in[12];
    const float* whl = (const float*)d_in[13];
    const int* eih   = (const int*)d_in[14];
    const int* eil   = (const int*)d_in[15];
    const int* batch = (const int*)d_in[16];
    float* out = (float*)d_out;

    void* pcnt;
    cudaGetSymbolAddress(&pcnt, g_dcnt);

    cudaFuncSetAttribute(gemm_hmma, cudaFuncAttributeMaxDynamicSharedMemorySize, SM_BYTES);

    // second stream + fork/join events (graph-capture-legal pattern)
    cudaStream_t s2;
    cudaStreamCreateWithFlags(&s2, cudaStreamNonBlocking);
    cudaEvent_t evFork, evCsr, evAttn, evPool;
    cudaEventCreateWithFlags(&evFork, cudaEventDisableTiming);
    cudaEventCreateWithFlags(&evCsr,  cudaEventDisableTiming);
    cudaEventCreateWithFlags(&evAttn, cudaEventDisableTiming);
    cudaEventCreateWithFlags(&evPool, cudaEventDisableTiming);

    cudaMemsetAsync(pcnt, 0, NT * sizeof(int), 0);
    cudaEventRecord(evFork, 0);
    cudaStreamWaitEvent(s2, evFork, 0);

    // stream s2: CSR build (independent of GEMM)
    edge_hist<<<(ET + 255) / 256, 256, 0, s2>>>(eih, eil);
    scan_local<<<NBLK, 1024, 0, s2>>>();
    scan_bsum<<<1, 512, 0, s2>>>();
    scan_add<<<NBLK, 1024, 0, s2>>>();
    edge_scatter<<<(ET + 255) / 256, 256, 0, s2>>>(eih, eil);
    cudaEventRecord(evCsr, s2);

    // stream 0: prep + GEMM (the long pole)
    prep_w<<<256, 256>>>(Wq, Wk, Wv, Ws);
    prep_b<<<2, 256>>>(bq, bk, bv, bs);
    gemm_hmma<<<NT / 128, 512, SM_BYTES>>>(high_emb, low_emb);

    // join: attention needs both GEMM outputs and CSR
    cudaStreamWaitEvent(0, evCsr, 0);
    dim3 t32x8(32, 8);
    attn_ln<<<NT / 8, t32x8>>>(lnw, lnb);
    cudaEventRecord(evAttn, 0);

    // overlap the two epilogues
    cudaStreamWaitEvent(s2, evAttn, 0);
    pool_final_high<<<NHI / 8, t32x8, 0, s2>>>(batch, wlh, out);
    cudaEventRecord(evPool, s2);
    final_low<<<NLO / 8, t32x8>>>(whl, batch, out + (size_t)NHI * DIM);
    cudaStreamWaitEvent(0, evPool, 0);

    cudaEventDestroy(evFork);
    cudaEventDestroy(evCsr);
    cudaEventDestroy(evAttn);
    cudaEventDestroy(evPool);
    cudaStreamDestroy(s2);
}